// round 5
// baseline (speedup 1.0000x reference)
#include <cuda_runtime.h>
#include <cuda_fp16.h>
#include <cstdint>

#define BB 4
#define NN 8192
#define DD 1024
#define HH 8
#define DK 128
#define BN (BB*NN)
#define SPLITS 8
#define CHS (NN/SPLITS)
#define EPSF 1e-5f
#define NKC (DD/64)            // 16 k-chunks of 64 halves
#define STAGE_B 49152u         // A(32KB)+B(16KB) per stage
#define GEMM_SMEM (3*STAGE_B)  // 147456

// Scratch (allocation-free device globals)
__device__ __half g_hq[(size_t)BN*DD];
__device__ __half g_hk[(size_t)BN*DD];
__device__ __half g_hv[(size_t)BN*DD];
__device__ __half g_hWk[(size_t)DD*DD];
__device__ __half g_hWv[(size_t)DD*DD];
__device__ __half g_Knh[(size_t)BB*HH*NN*DK];
__device__ __half g_Vnh[(size_t)BB*HH*NN*DK];
__device__ float  g_Spart[(size_t)SPLITS*BB*HH*DK*DK];
__device__ __half g_WeffTh[(size_t)BB*DD*DD];
__device__ float  g_beff[(size_t)BB*DD];

// ---------------------------------------------------------------------------
__device__ __forceinline__ uint32_t smem_u32(const void* p) {
    uint32_t a;
    asm("{ .reg .u64 t; cvta.to.shared.u64 t, %1; cvt.u32.u64 %0, t; }"
        : "=r"(a) : "l"(p));
    return a;
}
__device__ __forceinline__ void cp16(uint32_t smem, const void* g) {
    asm volatile("cp.async.cg.shared.global [%0], [%1], 16;"
                 :: "r"(smem), "l"(g));
}
#define CP_COMMIT() asm volatile("cp.async.commit_group;" ::: "memory")
#define CP_WAIT(n)  asm volatile("cp.async.wait_group %0;" :: "n"(n) : "memory")

__device__ __forceinline__ void ldsm4(uint32_t* r, uint32_t a) {
    asm volatile("ldmatrix.sync.aligned.m8n8.x4.shared.b16 {%0,%1,%2,%3}, [%4];"
                 : "=r"(r[0]), "=r"(r[1]), "=r"(r[2]), "=r"(r[3]) : "r"(a));
}
__device__ __forceinline__ void ldsm4t(uint32_t* r, uint32_t a) {
    asm volatile("ldmatrix.sync.aligned.m8n8.x4.trans.shared.b16 {%0,%1,%2,%3}, [%4];"
                 : "=r"(r[0]), "=r"(r[1]), "=r"(r[2]), "=r"(r[3]) : "r"(a));
}
__device__ __forceinline__ void mma16(float* d, const uint32_t* a, const uint32_t* b) {
    asm volatile(
        "mma.sync.aligned.m16n8k16.row.col.f32.f16.f16.f32 "
        "{%0,%1,%2,%3}, {%4,%5,%6,%7}, {%8,%9}, {%0,%1,%2,%3};"
        : "+f"(d[0]), "+f"(d[1]), "+f"(d[2]), "+f"(d[3])
        : "r"(a[0]), "r"(a[1]), "r"(a[2]), "r"(a[3]), "r"(b[0]), "r"(b[1]));
}

// ---------------------------------------------------------------------------
__global__ __launch_bounds__(256)
void f2h_kernel(const float* __restrict__ in, __half* __restrict__ out, int n8)
{
    int i = blockIdx.x * 256 + threadIdx.x;
    if (i >= n8) return;
    float4 x = ((const float4*)in)[2 * i];
    float4 y = ((const float4*)in)[2 * i + 1];
    __half2 h[4];
    h[0] = __floats2half2_rn(x.x, x.y);
    h[1] = __floats2half2_rn(x.z, x.w);
    h[2] = __floats2half2_rn(y.x, y.y);
    h[3] = __floats2half2_rn(y.z, y.w);
    ((uint4*)out)[i] = *(uint4*)h;
}

// ---------------------------------------------------------------------------
// Big GEMM, fp16 mma.sync: C[256,128] tile of A[BN,1024] @ B^T
// warps 4(M)x2(N), warp tile 64x64; 3-stage cp.async, 1 sync per chunk.
// mode 0: B=Wk(h) head jb -> bias+LN -> g_Knh
// mode 1: B=Wv(h) head jb -> bias+LN -> g_Vnh
// mode 2: B=g_WeffTh[b] block jb -> +g_beff -> out (fp32)
// ---------------------------------------------------------------------------
__global__ __launch_bounds__(256)
void gemm_h(const __half* __restrict__ A, const __half* __restrict__ Bmat,
            const float* __restrict__ bias, const float* __restrict__ gamma,
            const float* __restrict__ beta, float* __restrict__ outp, int mode)
{
    extern __shared__ float sm[];
    const int r0  = blockIdx.x * 256;
    const int jb  = blockIdx.y;
    const int b_  = r0 >> 13;
    const int tid = threadIdx.x;
    const int warp = tid >> 5, lane = tid & 31;
    const int wm = warp >> 1, wn = warp & 1;
    const int gid = lane >> 2, tig = lane & 3;

    const __half* Ap = A + (size_t)r0 * DD;
    const __half* Bp = (mode == 2)
        ? (g_WeffTh + (size_t)b_ * DD * DD + (size_t)jb * DK * DD)
        : (Bmat + (size_t)jb * DK * DD);

    const uint32_t smb = smem_u32(sm);

    float acc[4][8][4];
    #pragma unroll
    for (int mt = 0; mt < 4; mt++)
        #pragma unroll
        for (int nt = 0; nt < 8; nt++)
            #pragma unroll
            for (int i = 0; i < 4; i++) acc[mt][nt][i] = 0.f;

    auto load_stage = [&](int kc, int s) {
        uint32_t ab = smb + (uint32_t)s * STAGE_B;
        const __half* ga = Ap + kc * 64;
        const __half* gb = Bp + kc * 64;
        #pragma unroll
        for (int u = 0; u < 8; u++) {           // A: 256 rows x 128B
            int idx = u * 256 + tid;
            int row = idx >> 3, ch = idx & 7;
            uint32_t off = (uint32_t)(row * 128 + ((ch ^ (row & 7)) << 4));
            cp16(ab + off, ga + (size_t)row * DD + ch * 8);
        }
        #pragma unroll
        for (int u = 0; u < 4; u++) {           // B: 128 rows x 128B
            int idx = u * 256 + tid;
            int row = idx >> 3, ch = idx & 7;
            uint32_t off = (uint32_t)(row * 128 + ((ch ^ (row & 7)) << 4));
            cp16(ab + 32768u + off, gb + (size_t)row * DD + ch * 8);
        }
        CP_COMMIT();
    };

    load_stage(0, 0);
    load_stage(1, 1);

    int st = 0;                                  // stage of current chunk
    for (int kc = 0; kc < NKC; kc++) {
        if (kc < NKC - 1) { CP_WAIT(1); } else { CP_WAIT(0); }
        __syncthreads();
        if (kc + 2 < NKC) {
            int s2 = st + 2; if (s2 >= 3) s2 -= 3;
            load_stage(kc + 2, s2);
        }

        uint32_t ab = smb + (uint32_t)st * STAGE_B;
        uint32_t bb = ab + 32768u;
        #pragma unroll
        for (int ks = 0; ks < 4; ks++) {
            uint32_t afr[4][4];
            #pragma unroll
            for (int mt = 0; mt < 4; mt++) {
                int r = wm * 64 + mt * 16 + (lane & 15);
                int c = ks * 2 + (lane >> 4);
                ldsm4(afr[mt], ab + r * 128 + ((c ^ (r & 7)) << 4));
            }
            #pragma unroll
            for (int eb = 0; eb < 4; eb++) {
                int r = wn * 64 + eb * 16 + ((lane >> 4) << 3) + (lane & 7);
                int c = ks * 2 + ((lane >> 3) & 1);
                uint32_t bfr[4];
                ldsm4(bfr, bb + r * 128 + ((c ^ (r & 7)) << 4));
                #pragma unroll
                for (int mt = 0; mt < 4; mt++) {
                    mma16(acc[mt][eb * 2],     afr[mt], bfr);
                    mma16(acc[mt][eb * 2 + 1], afr[mt], bfr + 2);
                }
            }
        }
        if (++st == 3) st = 0;
    }

    if (mode == 2) {
        float2 bev[8];
        #pragma unroll
        for (int nt = 0; nt < 8; nt++)
            bev[nt] = *(const float2*)&g_beff[(size_t)b_ * DD + jb * DK
                                              + wn * 64 + nt * 8 + tig * 2];
        #pragma unroll
        for (int mt = 0; mt < 4; mt++)
            #pragma unroll
            for (int h = 0; h < 2; h++) {
                int row = wm * 64 + mt * 16 + gid + h * 8;
                float* op = outp + (size_t)(r0 + row) * DD + jb * DK;
                #pragma unroll
                for (int nt = 0; nt < 8; nt++) {
                    float2 o;
                    o.x = acc[mt][nt][2 * h + 0] + bev[nt].x;
                    o.y = acc[mt][nt][2 * h + 1] + bev[nt].y;
                    *(float2*)(op + wn * 64 + nt * 8 + tig * 2) = o;
                }
            }
        return;
    }

    // bias + per-row LN over 128 cols, fp16 out [B,H,N,dk]
    float2 bv[8], gv[8], ev[8];
    #pragma unroll
    for (int nt = 0; nt < 8; nt++) {
        int c = jb * DK + wn * 64 + nt * 8 + tig * 2;
        bv[nt] = *(const float2*)&bias[c];
        gv[nt] = *(const float2*)&gamma[c];
        ev[nt] = *(const float2*)&beta[c];
    }
    float s_[4][2], ss_[4][2];
    #pragma unroll
    for (int mt = 0; mt < 4; mt++)
        #pragma unroll
        for (int h = 0; h < 2; h++) { s_[mt][h] = 0.f; ss_[mt][h] = 0.f; }

    #pragma unroll
    for (int mt = 0; mt < 4; mt++)
        #pragma unroll
        for (int nt = 0; nt < 8; nt++) {
            acc[mt][nt][0] += bv[nt].x; acc[mt][nt][1] += bv[nt].y;
            acc[mt][nt][2] += bv[nt].x; acc[mt][nt][3] += bv[nt].y;
            #pragma unroll
            for (int h = 0; h < 2; h++) {
                float x0 = acc[mt][nt][2 * h], x1 = acc[mt][nt][2 * h + 1];
                s_[mt][h]  += x0 + x1;
                ss_[mt][h] += x0 * x0 + x1 * x1;
            }
        }
    #pragma unroll
    for (int mt = 0; mt < 4; mt++)
        #pragma unroll
        for (int h = 0; h < 2; h++) {
            #pragma unroll
            for (int o = 1; o <= 2; o <<= 1) {
                s_[mt][h]  += __shfl_xor_sync(0xFFFFFFFFu, s_[mt][h],  o);
                ss_[mt][h] += __shfl_xor_sync(0xFFFFFFFFu, ss_[mt][h], o);
            }
        }

    __syncthreads();                 // stages fully consumed; reuse smem
    float* red = sm;                 // [256 rows][wn][2]
    if (tig == 0) {
        #pragma unroll
        for (int mt = 0; mt < 4; mt++)
            #pragma unroll
            for (int h = 0; h < 2; h++) {
                int row = wm * 64 + mt * 16 + gid + h * 8;
                red[(row * 2 + wn) * 2 + 0] = s_[mt][h];
                red[(row * 2 + wn) * 2 + 1] = ss_[mt][h];
            }
    }
    __syncthreads();

    __half* dst = mode ? g_Vnh : g_Knh;
    #pragma unroll
    for (int mt = 0; mt < 4; mt++)
        #pragma unroll
        for (int h = 0; h < 2; h++) {
            int row = wm * 64 + mt * 16 + gid + h * 8;
            float st_  = red[(row * 2 + 0) * 2 + 0] + red[(row * 2 + 1) * 2 + 0];
            float sst = red[(row * 2 + 0) * 2 + 1] + red[(row * 2 + 1) * 2 + 1];
            float mean = st_ * (1.f / DK);
            float var  = sst * (1.f / DK) - mean * mean;
            float inv  = rsqrtf(var + EPSF);
            int r  = r0 + row;
            __half* op = dst + (((size_t)(b_ * HH + jb)) * NN + (r & (NN - 1))) * DK;
            #pragma unroll
            for (int nt = 0; nt < 8; nt++) {
                float ox = (acc[mt][nt][2*h+0] - mean) * inv * gv[nt].x + ev[nt].x;
                float oy = (acc[mt][nt][2*h+1] - mean) * inv * gv[nt].y + ev[nt].y;
                *(__half2*)(op + wn * 64 + nt * 8 + tig * 2) = __floats2half2_rn(ox, oy);
            }
        }
}

// ---------------------------------------------------------------------------
// scores on fp16 mma (unchanged from round 4)
// ---------------------------------------------------------------------------
__global__ __launch_bounds__(256)
void scores_h()
{
    extern __shared__ float sm[];
    const int split = blockIdx.x;
    const int bh    = blockIdx.y;
    const int tid = threadIdx.x;
    const int warp = tid >> 5, lane = tid & 31;
    const int wm = warp >> 1, wn = warp & 1;
    const int gid = lane >> 2, tig = lane & 3;

    const size_t base = (size_t)bh * NN * DK + (size_t)split * CHS * DK;
    const uint32_t smb = smem_u32(sm);

    float acc[2][8][4];
    #pragma unroll
    for (int mt = 0; mt < 2; mt++)
        #pragma unroll
        for (int nt = 0; nt < 8; nt++)
            #pragma unroll
            for (int i = 0; i < 4; i++) acc[mt][nt][i] = 0.f;

    auto load_stage = [&](int kc, int s) {
        uint32_t kb = smb + (uint32_t)s * 16384u;
        const __half* gk = g_Knh + base + (size_t)kc * 32 * DK;
        const __half* gv = g_Vnh + base + (size_t)kc * 32 * DK;
        #pragma unroll
        for (int u = 0; u < 2; u++) {
            int idx = u * 256 + tid;
            int row = idx >> 4, ch = idx & 15;
            uint32_t off = (uint32_t)(row * 256 + ((ch ^ (row & 7)) << 4));
            cp16(kb + off,          gk + (size_t)row * DK + ch * 8);
            cp16(kb + 8192u + off,  gv + (size_t)row * DK + ch * 8);
        }
        CP_COMMIT();
    };

    const int NCH = CHS / 32;
    load_stage(0, 0);

    for (int kc = 0; kc < NCH; kc++) {
        if (kc + 1 < NCH) { load_stage(kc + 1, (kc + 1) & 1); CP_WAIT(1); }
        else              { CP_WAIT(0); }
        __syncthreads();

        uint32_t kb = smb + (uint32_t)(kc & 1) * 16384u;
        uint32_t vb = kb + 8192u;
        #pragma unroll
        for (int step = 0; step < 2; step++) {
            int n0 = step * 16;
            uint32_t afr[2][4];
            #pragma unroll
            for (int mt = 0; mt < 2; mt++) {
                int m0 = wm * 32 + mt * 16;
                int r = n0 + ((lane >> 4) << 3) + (lane & 7);
                int c = (m0 >> 3) + ((lane >> 3) & 1);
                ldsm4t(afr[mt], kb + r * 256 + ((c ^ (r & 7)) << 4));
            }
            #pragma unroll
            for (int eb = 0; eb < 4; eb++) {
                int e0 = wn * 64 + eb * 16;
                int r = n0 + (((lane >> 3) & 1) << 3) + (lane & 7);
                int c = (e0 >> 3) + (lane >> 4);
                uint32_t bfr[4];
                ldsm4t(bfr, vb + r * 256 + ((c ^ (r & 7)) << 4));
                mma16(acc[0][eb * 2],     afr[0], bfr);
                mma16(acc[0][eb * 2 + 1], afr[0], bfr + 2);
                mma16(acc[1][eb * 2],     afr[1], bfr);
                mma16(acc[1][eb * 2 + 1], afr[1], bfr + 2);
            }
        }
        __syncthreads();
    }

    size_t pbase = ((size_t)split * (BB * HH) + bh) * DK * DK;
    #pragma unroll
    for (int mt = 0; mt < 2; mt++)
        #pragma unroll
        for (int h = 0; h < 2; h++) {
            int row = wm * 32 + mt * 16 + gid + h * 8;
            #pragma unroll
            for (int nt = 0; nt < 8; nt++) {
                float2 o;
                o.x = acc[mt][nt][2 * h + 0];
                o.y = acc[mt][nt][2 * h + 1];
                *(float2*)&g_Spart[pbase + (size_t)row * DK
                                   + wn * 64 + nt * 8 + tig * 2] = o;
            }
        }
}

__global__ void reduce_scores_kernel(float* __restrict__ p_out)
{
    int i = blockIdx.x * 256 + threadIdx.x;
    float s = 0.f;
    #pragma unroll
    for (int sp = 0; sp < SPLITS; sp++)
        s += g_Spart[(size_t)sp * (BB * HH * DK * DK) + i];
    p_out[i] = s * (1.f / NN);
}

__global__ void beff_kernel(const float* __restrict__ bq, const float* __restrict__ p)
{
    int bh = blockIdx.x;
    int e  = threadIdx.x;
    int h  = bh & (HH - 1), b_ = bh >> 3;
    const float* pp = p + (size_t)bh * DK * DK;
    float s = 0.f;
    #pragma unroll 8
    for (int d = 0; d < DK; d++) s += bq[h * DK + d] * pp[(size_t)d * DK + e];
    g_beff[(size_t)b_ * DD + h * DK + e] = s;
}

__global__ __launch_bounds__(256)
void weff_kernel(const float* __restrict__ Wq, const float* __restrict__ p)
{
    const int c0 = blockIdx.x * 64;
    const int bh = blockIdx.y;
    const int h = bh & (HH - 1), b_ = bh >> 3;
    const int tid = threadIdx.x;
    const int ty = tid >> 4, tx = tid & 15;

    __shared__ float As[16][64];
    __shared__ float Bs[16][128];

    float acc[4][8];
    #pragma unroll
    for (int i = 0; i < 4; i++)
        #pragma unroll
        for (int j = 0; j < 8; j++) acc[i][j] = 0.f;

    const int ak = tid >> 4;
    const int ar = (tid & 15) * 4;
    const int bk = tid >> 4;
    const int bc = (tid & 15) * 8;

    for (int k0 = 0; k0 < DK; k0 += 16) {
        *(float4*)&As[ak][ar] =
            *(const float4*)&Wq[(size_t)(h * DK + k0 + ak) * DD + c0 + ar];
        const float* pp = &p[(size_t)bh * DK * DK + (size_t)(k0 + bk) * DK + bc];
        *(float4*)&Bs[bk][bc]     = *(const float4*)pp;
        *(float4*)&Bs[bk][bc + 4] = *(const float4*)(pp + 4);
        __syncthreads();

        #pragma unroll
        for (int kk = 0; kk < 16; kk++) {
            float a[4], b[8];
            *(float4*)a       = *(const float4*)&As[kk][ty * 4];
            *(float4*)b       = *(const float4*)&Bs[kk][tx * 8];
            *(float4*)(b + 4) = *(const float4*)&Bs[kk][tx * 8 + 4];
            #pragma unroll
            for (int i = 0; i < 4; i++)
                #pragma unroll
                for (int j = 0; j < 8; j++) acc[i][j] += a[i] * b[j];
        }
        __syncthreads();
    }

    #pragma unroll
    for (int i = 0; i < 4; i++)
        #pragma unroll
        for (int j = 0; j < 8; j++)
            g_WeffTh[(size_t)b_ * DD * DD
                     + (size_t)(h * DK + tx * 8 + j) * DD + (c0 + ty * 4 + i)]
                = __float2half_rn(acc[i][j]);
}

extern "C" void kernel_launch(void* const* d_in, const int* in_sizes, int n_in,
                              void* d_out, int out_size)
{
    const float* q   = (const float*)d_in[0];
    const float* k   = (const float*)d_in[1];
    const float* v   = (const float*)d_in[2];
    const float* Wq  = (const float*)d_in[3];
    const float* bq  = (const float*)d_in[4];
    const float* Wk  = (const float*)d_in[5];
    const float* bk  = (const float*)d_in[6];
    const float* Wv  = (const float*)d_in[7];
    const float* bv  = (const float*)d_in[8];
    const float* gK  = (const float*)d_in[9];
    const float* beK = (const float*)d_in[10];
    const float* gV  = (const float*)d_in[11];
    const float* beV = (const float*)d_in[12];

    float* out   = (float*)d_out;
    float* p_out = out + (size_t)BN * DD;

    static bool attr_done = false;
    if (!attr_done) {
        cudaFuncSetAttribute(gemm_h, cudaFuncAttributeMaxDynamicSharedMemorySize, GEMM_SMEM);
        cudaFuncSetAttribute(scores_h, cudaFuncAttributeMaxDynamicSharedMemorySize, 32768);
        attr_done = true;
    }

    __half *hq, *hk, *hv, *hWk, *hWv;
    cudaGetSymbolAddress((void**)&hq,  g_hq);
    cudaGetSymbolAddress((void**)&hk,  g_hk);
    cudaGetSymbolAddress((void**)&hv,  g_hv);
    cudaGetSymbolAddress((void**)&hWk, g_hWk);
    cudaGetSymbolAddress((void**)&hWv, g_hWv);

    const int n8_big = (BN * DD) / 8;
    const int n8_w   = (DD * DD) / 8;
    f2h_kernel<<<(n8_big + 255) / 256, 256>>>(q, hq, n8_big);
    f2h_kernel<<<(n8_big + 255) / 256, 256>>>(k, hk, n8_big);
    f2h_kernel<<<(n8_big + 255) / 256, 256>>>(v, hv, n8_big);
    f2h_kernel<<<(n8_w + 255) / 256, 256>>>(Wk, hWk, n8_w);
    f2h_kernel<<<(n8_w + 255) / 256, 256>>>(Wv, hWv, n8_w);

    dim3 gg(BN / 256, HH);
    gemm_h<<<gg, 256, GEMM_SMEM>>>(hk, hWk, bk, gK, beK, nullptr, 0);
    gemm_h<<<gg, 256, GEMM_SMEM>>>(hv, hWv, bv, gV, beV, nullptr, 1);
    scores_h<<<dim3(SPLITS, BB * HH), 256, 32768>>>();
    reduce_scores_kernel<<<dim3((BB * HH * DK * DK) / 256), 256>>>(p_out);
    beff_kernel<<<dim3(BB * HH), dim3(DK)>>>(bq, p_out);
    weff_kernel<<<dim3(DD / 64, BB * HH), 256>>>(Wq, p_out);
    gemm_h<<<gg, 256, GEMM_SMEM>>>(hq, nullptr, nullptr, nullptr, nullptr, out, 2);
}

// round 6
// speedup vs baseline: 1.1259x; 1.1259x over previous
#include <cuda_runtime.h>
#include <cuda_fp16.h>
#include <cstdint>

#define BB 4
#define NN 8192
#define DD 1024
#define HH 8
#define DK 128
#define BN (BB*NN)
#define SPLITS 8
#define CHS (NN/SPLITS)
#define EPSF 1e-5f
#define NKC (DD/64)            // 16 k-chunks of 64 halves
#define STAGE_B 32768u         // A(16KB)+B(16KB) per stage
#define GEMM_SMEM (3*STAGE_B)  // 98304 -> 2 CTAs/SM

// Scratch (allocation-free device globals)
__device__ __half g_hq[(size_t)BN*DD];
__device__ __half g_hk[(size_t)BN*DD];
__device__ __half g_hv[(size_t)BN*DD];
__device__ __half g_hWk[(size_t)DD*DD];
__device__ __half g_hWv[(size_t)DD*DD];
__device__ __half g_Knh[(size_t)BB*HH*NN*DK];
__device__ __half g_Vnh[(size_t)BB*HH*NN*DK];
__device__ float  g_Spart[(size_t)SPLITS*BB*HH*DK*DK];
__device__ __half g_WeffTh[(size_t)BB*DD*DD];
__device__ float  g_beff[(size_t)BB*DD];

// ---------------------------------------------------------------------------
__device__ __forceinline__ uint32_t smem_u32(const void* p) {
    uint32_t a;
    asm("{ .reg .u64 t; cvta.to.shared.u64 t, %1; cvt.u32.u64 %0, t; }"
        : "=r"(a) : "l"(p));
    return a;
}
__device__ __forceinline__ void cp16(uint32_t smem, const void* g) {
    asm volatile("cp.async.cg.shared.global [%0], [%1], 16;"
                 :: "r"(smem), "l"(g));
}
#define CP_COMMIT() asm volatile("cp.async.commit_group;" ::: "memory")
#define CP_WAIT(n)  asm volatile("cp.async.wait_group %0;" :: "n"(n) : "memory")

__device__ __forceinline__ void ldsm4(uint32_t* r, uint32_t a) {
    asm volatile("ldmatrix.sync.aligned.m8n8.x4.shared.b16 {%0,%1,%2,%3}, [%4];"
                 : "=r"(r[0]), "=r"(r[1]), "=r"(r[2]), "=r"(r[3]) : "r"(a));
}
__device__ __forceinline__ void ldsm4t(uint32_t* r, uint32_t a) {
    asm volatile("ldmatrix.sync.aligned.m8n8.x4.trans.shared.b16 {%0,%1,%2,%3}, [%4];"
                 : "=r"(r[0]), "=r"(r[1]), "=r"(r[2]), "=r"(r[3]) : "r"(a));
}
__device__ __forceinline__ void mma16(float* d, const uint32_t* a, const uint32_t* b) {
    asm volatile(
        "mma.sync.aligned.m16n8k16.row.col.f32.f16.f16.f32 "
        "{%0,%1,%2,%3}, {%4,%5,%6,%7}, {%8,%9}, {%0,%1,%2,%3};"
        : "+f"(d[0]), "+f"(d[1]), "+f"(d[2]), "+f"(d[3])
        : "r"(a[0]), "r"(a[1]), "r"(a[2]), "r"(a[3]), "r"(b[0]), "r"(b[1]));
}

// ---------------------------------------------------------------------------
// fused fp32->fp16 convert of q,k,v (grid-stride, 8 elems/thread)
// ---------------------------------------------------------------------------
__global__ __launch_bounds__(256)
void f2h3_kernel(const float* __restrict__ a, const float* __restrict__ b,
                 const float* __restrict__ c, int n8)
{
    int i = blockIdx.x * 256 + threadIdx.x;
    int which = i / n8;
    int idx = i - which * n8;
    const float* in = (which == 0) ? a : (which == 1) ? b : c;
    __half* out = (which == 0) ? g_hq : (which == 1) ? g_hk : g_hv;
    float4 x = ((const float4*)in)[2 * idx];
    float4 y = ((const float4*)in)[2 * idx + 1];
    __half2 h[4];
    h[0] = __floats2half2_rn(x.x, x.y);
    h[1] = __floats2half2_rn(x.z, x.w);
    h[2] = __floats2half2_rn(y.x, y.y);
    h[3] = __floats2half2_rn(y.z, y.w);
    ((uint4*)out)[idx] = *(uint4*)h;
}

__global__ __launch_bounds__(256)
void f2h_kernel(const float* __restrict__ in, __half* __restrict__ out, int n8)
{
    int i = blockIdx.x * 256 + threadIdx.x;
    if (i >= n8) return;
    float4 x = ((const float4*)in)[2 * i];
    float4 y = ((const float4*)in)[2 * i + 1];
    __half2 h[4];
    h[0] = __floats2half2_rn(x.x, x.y);
    h[1] = __floats2half2_rn(x.z, x.w);
    h[2] = __floats2half2_rn(y.x, y.y);
    h[3] = __floats2half2_rn(y.z, y.w);
    ((uint4*)out)[i] = *(uint4*)h;
}

// ---------------------------------------------------------------------------
// Big GEMM, fp16 mma.sync: C[128,128] tile of A[BN,1024] @ B^T
// warps 4(M)x2(N), warp tile 32x64; 3-stage cp.async, ONE sync per chunk.
// mode 0: B=Wk(h) head jb -> bias+LN -> g_Knh
// mode 1: B=Wv(h) head jb -> bias+LN -> g_Vnh
// mode 2: B=g_WeffTh[b] block jb -> +g_beff -> out (fp32)
// ---------------------------------------------------------------------------
__global__ __launch_bounds__(256)
void gemm_h(const __half* __restrict__ A, const __half* __restrict__ Bmat,
            const float* __restrict__ bias, const float* __restrict__ gamma,
            const float* __restrict__ beta, float* __restrict__ outp, int mode)
{
    extern __shared__ float sm[];
    const int r0  = blockIdx.x * 128;
    const int jb  = blockIdx.y;
    const int b_  = r0 >> 13;
    const int tid = threadIdx.x;
    const int warp = tid >> 5, lane = tid & 31;
    const int wm = warp >> 1, wn = warp & 1;
    const int gid = lane >> 2, tig = lane & 3;

    const __half* Ap = A + (size_t)r0 * DD;
    const __half* Bp = (mode == 2)
        ? (g_WeffTh + (size_t)b_ * DD * DD + (size_t)jb * DK * DD)
        : (Bmat + (size_t)jb * DK * DD);

    const uint32_t smb = smem_u32(sm);

    float acc[2][8][4];
    #pragma unroll
    for (int mt = 0; mt < 2; mt++)
        #pragma unroll
        for (int nt = 0; nt < 8; nt++)
            #pragma unroll
            for (int i = 0; i < 4; i++) acc[mt][nt][i] = 0.f;

    auto load_stage = [&](int kc, int s) {
        uint32_t base = smb + (uint32_t)s * STAGE_B;
        const __half* ga = Ap + kc * 64;
        const __half* gb = Bp + kc * 64;
        #pragma unroll
        for (int u = 0; u < 4; u++) {
            int idx = u * 256 + tid;
            int row = idx >> 3, ch = idx & 7;
            uint32_t off = (uint32_t)(row * 128 + ((ch ^ (row & 7)) << 4));
            cp16(base + off,           ga + (size_t)row * DD + ch * 8);
            cp16(base + 16384u + off,  gb + (size_t)row * DD + ch * 8);
        }
        CP_COMMIT();
    };

    load_stage(0, 0);
    load_stage(1, 1);

    int st = 0;
    for (int kc = 0; kc < NKC; kc++) {
        if (kc < NKC - 1) { CP_WAIT(1); } else { CP_WAIT(0); }
        __syncthreads();
        if (kc + 2 < NKC) {
            int s2 = st + 2; if (s2 >= 3) s2 -= 3;
            load_stage(kc + 2, s2);
        }

        uint32_t ab = smb + (uint32_t)st * STAGE_B;
        uint32_t bb = ab + 16384u;
        #pragma unroll
        for (int ks = 0; ks < 4; ks++) {
            uint32_t afr[2][4];
            #pragma unroll
            for (int mt = 0; mt < 2; mt++) {
                int r = wm * 32 + mt * 16 + (lane & 15);
                int c = ks * 2 + (lane >> 4);
                ldsm4(afr[mt], ab + r * 128 + ((c ^ (r & 7)) << 4));
            }
            #pragma unroll
            for (int eb = 0; eb < 4; eb++) {
                int r = wn * 64 + eb * 16 + ((lane >> 4) << 3) + (lane & 7);
                int c = ks * 2 + ((lane >> 3) & 1);
                uint32_t bfr[4];
                ldsm4(bfr, bb + r * 128 + ((c ^ (r & 7)) << 4));
                mma16(acc[0][eb * 2],     afr[0], bfr);
                mma16(acc[0][eb * 2 + 1], afr[0], bfr + 2);
                mma16(acc[1][eb * 2],     afr[1], bfr);
                mma16(acc[1][eb * 2 + 1], afr[1], bfr + 2);
            }
        }
        if (++st == 3) st = 0;
    }

    if (mode == 2) {
        float2 bev[8];
        #pragma unroll
        for (int nt = 0; nt < 8; nt++)
            bev[nt] = *(const float2*)&g_beff[(size_t)b_ * DD + jb * DK
                                              + wn * 64 + nt * 8 + tig * 2];
        #pragma unroll
        for (int mt = 0; mt < 2; mt++)
            #pragma unroll
            for (int h = 0; h < 2; h++) {
                int row = wm * 32 + mt * 16 + gid + h * 8;
                float* op = outp + (size_t)(r0 + row) * DD + jb * DK;
                #pragma unroll
                for (int nt = 0; nt < 8; nt++) {
                    float2 o;
                    o.x = acc[mt][nt][2 * h + 0] + bev[nt].x;
                    o.y = acc[mt][nt][2 * h + 1] + bev[nt].y;
                    *(float2*)(op + wn * 64 + nt * 8 + tig * 2) = o;
                }
            }
        return;
    }

    // bias + per-row LN over 128 cols, fp16 out [B,H,N,dk]
    float2 bv[8], gv[8], ev[8];
    #pragma unroll
    for (int nt = 0; nt < 8; nt++) {
        int c = jb * DK + wn * 64 + nt * 8 + tig * 2;
        bv[nt] = *(const float2*)&bias[c];
        gv[nt] = *(const float2*)&gamma[c];
        ev[nt] = *(const float2*)&beta[c];
    }
    float s_[2][2], ss_[2][2];
    #pragma unroll
    for (int mt = 0; mt < 2; mt++)
        #pragma unroll
        for (int h = 0; h < 2; h++) { s_[mt][h] = 0.f; ss_[mt][h] = 0.f; }

    #pragma unroll
    for (int mt = 0; mt < 2; mt++)
        #pragma unroll
        for (int nt = 0; nt < 8; nt++) {
            acc[mt][nt][0] += bv[nt].x; acc[mt][nt][1] += bv[nt].y;
            acc[mt][nt][2] += bv[nt].x; acc[mt][nt][3] += bv[nt].y;
            #pragma unroll
            for (int h = 0; h < 2; h++) {
                float x0 = acc[mt][nt][2 * h], x1 = acc[mt][nt][2 * h + 1];
                s_[mt][h]  += x0 + x1;
                ss_[mt][h] += x0 * x0 + x1 * x1;
            }
        }
    #pragma unroll
    for (int mt = 0; mt < 2; mt++)
        #pragma unroll
        for (int h = 0; h < 2; h++) {
            #pragma unroll
            for (int o = 1; o <= 2; o <<= 1) {
                s_[mt][h]  += __shfl_xor_sync(0xFFFFFFFFu, s_[mt][h],  o);
                ss_[mt][h] += __shfl_xor_sync(0xFFFFFFFFu, ss_[mt][h], o);
            }
        }

    __syncthreads();
    float* red = sm;
    if (tig == 0) {
        #pragma unroll
        for (int mt = 0; mt < 2; mt++)
            #pragma unroll
            for (int h = 0; h < 2; h++) {
                int row = wm * 32 + mt * 16 + gid + h * 8;
                red[(row * 2 + wn) * 2 + 0] = s_[mt][h];
                red[(row * 2 + wn) * 2 + 1] = ss_[mt][h];
            }
    }
    __syncthreads();

    __half* dst = mode ? g_Vnh : g_Knh;
    #pragma unroll
    for (int mt = 0; mt < 2; mt++)
        #pragma unroll
        for (int h = 0; h < 2; h++) {
            int row = wm * 32 + mt * 16 + gid + h * 8;
            float st_ = red[(row * 2 + 0) * 2 + 0] + red[(row * 2 + 1) * 2 + 0];
            float sst = red[(row * 2 + 0) * 2 + 1] + red[(row * 2 + 1) * 2 + 1];
            float mean = st_ * (1.f / DK);
            float var  = sst * (1.f / DK) - mean * mean;
            float inv  = rsqrtf(var + EPSF);
            int r  = r0 + row;
            __half* op = dst + (((size_t)(b_ * HH + jb)) * NN + (r & (NN - 1))) * DK;
            #pragma unroll
            for (int nt = 0; nt < 8; nt++) {
                float ox = (acc[mt][nt][2*h+0] - mean) * inv * gv[nt].x + ev[nt].x;
                float oy = (acc[mt][nt][2*h+1] - mean) * inv * gv[nt].y + ev[nt].y;
                *(__half2*)(op + wn * 64 + nt * 8 + tig * 2) = __floats2half2_rn(ox, oy);
            }
        }
}

// ---------------------------------------------------------------------------
// scores on fp16 mma (round-4 version)
// ---------------------------------------------------------------------------
__global__ __launch_bounds__(256)
void scores_h()
{
    extern __shared__ float sm[];
    const int split = blockIdx.x;
    const int bh    = blockIdx.y;
    const int tid = threadIdx.x;
    const int warp = tid >> 5, lane = tid & 31;
    const int wm = warp >> 1, wn = warp & 1;
    const int gid = lane >> 2, tig = lane & 3;

    const size_t base = (size_t)bh * NN * DK + (size_t)split * CHS * DK;
    const uint32_t smb = smem_u32(sm);

    float acc[2][8][4];
    #pragma unroll
    for (int mt = 0; mt < 2; mt++)
        #pragma unroll
        for (int nt = 0; nt < 8; nt++)
            #pragma unroll
            for (int i = 0; i < 4; i++) acc[mt][nt][i] = 0.f;

    auto load_stage = [&](int kc, int s) {
        uint32_t kb = smb + (uint32_t)s * 16384u;
        const __half* gk = g_Knh + base + (size_t)kc * 32 * DK;
        const __half* gv = g_Vnh + base + (size_t)kc * 32 * DK;
        #pragma unroll
        for (int u = 0; u < 2; u++) {
            int idx = u * 256 + tid;
            int row = idx >> 4, ch = idx & 15;
            uint32_t off = (uint32_t)(row * 256 + ((ch ^ (row & 7)) << 4));
            cp16(kb + off,          gk + (size_t)row * DK + ch * 8);
            cp16(kb + 8192u + off,  gv + (size_t)row * DK + ch * 8);
        }
        CP_COMMIT();
    };

    const int NCH = CHS / 32;
    load_stage(0, 0);

    for (int kc = 0; kc < NCH; kc++) {
        if (kc + 1 < NCH) { load_stage(kc + 1, (kc + 1) & 1); CP_WAIT(1); }
        else              { CP_WAIT(0); }
        __syncthreads();

        uint32_t kb = smb + (uint32_t)(kc & 1) * 16384u;
        uint32_t vb = kb + 8192u;
        #pragma unroll
        for (int step = 0; step < 2; step++) {
            int n0 = step * 16;
            uint32_t afr[2][4];
            #pragma unroll
            for (int mt = 0; mt < 2; mt++) {
                int m0 = wm * 32 + mt * 16;
                int r = n0 + ((lane >> 4) << 3) + (lane & 7);
                int c = (m0 >> 3) + ((lane >> 3) & 1);
                ldsm4t(afr[mt], kb + r * 256 + ((c ^ (r & 7)) << 4));
            }
            #pragma unroll
            for (int eb = 0; eb < 4; eb++) {
                int e0 = wn * 64 + eb * 16;
                int r = n0 + (((lane >> 3) & 1) << 3) + (lane & 7);
                int c = (e0 >> 3) + (lane >> 4);
                uint32_t bfr[4];
                ldsm4t(bfr, vb + r * 256 + ((c ^ (r & 7)) << 4));
                mma16(acc[0][eb * 2],     afr[0], bfr);
                mma16(acc[0][eb * 2 + 1], afr[0], bfr + 2);
                mma16(acc[1][eb * 2],     afr[1], bfr);
                mma16(acc[1][eb * 2 + 1], afr[1], bfr + 2);
            }
        }
        __syncthreads();
    }

    size_t pbase = ((size_t)split * (BB * HH) + bh) * DK * DK;
    #pragma unroll
    for (int mt = 0; mt < 2; mt++)
        #pragma unroll
        for (int h = 0; h < 2; h++) {
            int row = wm * 32 + mt * 16 + gid + h * 8;
            #pragma unroll
            for (int nt = 0; nt < 8; nt++) {
                float2 o;
                o.x = acc[mt][nt][2 * h + 0];
                o.y = acc[mt][nt][2 * h + 1];
                *(float2*)&g_Spart[pbase + (size_t)row * DK
                                   + wn * 64 + nt * 8 + tig * 2] = o;
            }
        }
}

__global__ void reduce_scores_kernel(float* __restrict__ p_out)
{
    int i = blockIdx.x * 256 + threadIdx.x;
    float s = 0.f;
    #pragma unroll
    for (int sp = 0; sp < SPLITS; sp++)
        s += g_Spart[(size_t)sp * (BB * HH * DK * DK) + i];
    p_out[i] = s * (1.f / NN);
}

__global__ void beff_kernel(const float* __restrict__ bq, const float* __restrict__ p)
{
    int bh = blockIdx.x;
    int e  = threadIdx.x;
    int h  = bh & (HH - 1), b_ = bh >> 3;
    const float* pp = p + (size_t)bh * DK * DK;
    float s = 0.f;
    #pragma unroll 8
    for (int d = 0; d < DK; d++) s += bq[h * DK + d] * pp[(size_t)d * DK + e];
    g_beff[(size_t)b_ * DD + h * DK + e] = s;
}

__global__ __launch_bounds__(256)
void weff_kernel(const float* __restrict__ Wq, const float* __restrict__ p)
{
    const int c0 = blockIdx.x * 64;
    const int bh = blockIdx.y;
    const int h = bh & (HH - 1), b_ = bh >> 3;
    const int tid = threadIdx.x;
    const int ty = tid >> 4, tx = tid & 15;

    __shared__ float As[16][64];
    __shared__ float Bs[16][128];

    float acc[4][8];
    #pragma unroll
    for (int i = 0; i < 4; i++)
        #pragma unroll
        for (int j = 0; j < 8; j++) acc[i][j] = 0.f;

    const int ak = tid >> 4;
    const int ar = (tid & 15) * 4;
    const int bk = tid >> 4;
    const int bc = (tid & 15) * 8;

    for (int k0 = 0; k0 < DK; k0 += 16) {
        *(float4*)&As[ak][ar] =
            *(const float4*)&Wq[(size_t)(h * DK + k0 + ak) * DD + c0 + ar];
        const float* pp = &p[(size_t)bh * DK * DK + (size_t)(k0 + bk) * DK + bc];
        *(float4*)&Bs[bk][bc]     = *(const float4*)pp;
        *(float4*)&Bs[bk][bc + 4] = *(const float4*)(pp + 4);
        __syncthreads();

        #pragma unroll
        for (int kk = 0; kk < 16; kk++) {
            float a[4], b[8];
            *(float4*)a       = *(const float4*)&As[kk][ty * 4];
            *(float4*)b       = *(const float4*)&Bs[kk][tx * 8];
            *(float4*)(b + 4) = *(const float4*)&Bs[kk][tx * 8 + 4];
            #pragma unroll
            for (int i = 0; i < 4; i++)
                #pragma unroll
                for (int j = 0; j < 8; j++) acc[i][j] += a[i] * b[j];
        }
        __syncthreads();
    }

    #pragma unroll
    for (int i = 0; i < 4; i++)
        #pragma unroll
        for (int j = 0; j < 8; j++)
            g_WeffTh[(size_t)b_ * DD * DD
                     + (size_t)(h * DK + tx * 8 + j) * DD + (c0 + ty * 4 + i)]
                = __float2half_rn(acc[i][j]);
}

extern "C" void kernel_launch(void* const* d_in, const int* in_sizes, int n_in,
                              void* d_out, int out_size)
{
    const float* q   = (const float*)d_in[0];
    const float* k   = (const float*)d_in[1];
    const float* v   = (const float*)d_in[2];
    const float* Wq  = (const float*)d_in[3];
    const float* bq  = (const float*)d_in[4];
    const float* Wk  = (const float*)d_in[5];
    const float* bk  = (const float*)d_in[6];
    const float* Wv  = (const float*)d_in[7];
    const float* bv  = (const float*)d_in[8];
    const float* gK  = (const float*)d_in[9];
    const float* beK = (const float*)d_in[10];
    const float* gV  = (const float*)d_in[11];
    const float* beV = (const float*)d_in[12];

    float* out   = (float*)d_out;
    float* p_out = out + (size_t)BN * DD;

    static bool attr_done = false;
    if (!attr_done) {
        cudaFuncSetAttribute(gemm_h, cudaFuncAttributeMaxDynamicSharedMemorySize, GEMM_SMEM);
        cudaFuncSetAttribute(scores_h, cudaFuncAttributeMaxDynamicSharedMemorySize, 32768);
        attr_done = true;
    }

    __half *hq, *hk, *hv, *hWk, *hWv;
    cudaGetSymbolAddress((void**)&hq,  g_hq);
    cudaGetSymbolAddress((void**)&hk,  g_hk);
    cudaGetSymbolAddress((void**)&hv,  g_hv);
    cudaGetSymbolAddress((void**)&hWk, g_hWk);
    cudaGetSymbolAddress((void**)&hWv, g_hWv);

    const int n8_big = (BN * DD) / 8;
    const int n8_w   = (DD * DD) / 8;
    f2h3_kernel<<<(3 * n8_big) / 256, 256>>>(q, k, v, n8_big);
    f2h_kernel<<<(n8_w + 255) / 256, 256>>>(Wk, hWk, n8_w);
    f2h_kernel<<<(n8_w + 255) / 256, 256>>>(Wv, hWv, n8_w);

    dim3 gg(BN / 128, HH);
    gemm_h<<<gg, 256, GEMM_SMEM>>>(hk, hWk, bk, gK, beK, nullptr, 0);
    gemm_h<<<gg, 256, GEMM_SMEM>>>(hv, hWv, bv, gV, beV, nullptr, 1);
    scores_h<<<dim3(SPLITS, BB * HH), 256, 32768>>>();
    reduce_scores_kernel<<<dim3((BB * HH * DK * DK) / 256), 256>>>(p_out);
    beff_kernel<<<dim3(BB * HH), dim3(DK)>>>(bq, p_out);
    weff_kernel<<<dim3(DD / 64, BB * HH), 256>>>(Wq, p_out);
    gemm_h<<<gg, 256, GEMM_SMEM>>>(hq, nullptr, nullptr, nullptr, nullptr, out, 2);
}

// round 7
// speedup vs baseline: 1.1295x; 1.0032x over previous
#include <cuda_runtime.h>
#include <cuda_fp16.h>
#include <cstdint>

#define BB 4
#define NN 8192
#define DD 1024
#define HH 8
#define DK 128
#define BN (BB*NN)
#define SPLITS 8
#define CHS (NN/SPLITS)
#define EPSF 1e-5f
#define NKC (DD/64)            // 16 k-chunks of 64 halves
#define STAGE_B 32768u         // A(16KB)+B(16KB) per stage
#define GEMM_SMEM (3*STAGE_B)  // 98304 -> 2 CTAs/SM

// Scratch (allocation-free device globals)
__device__ __half g_hq[(size_t)BN*DD];
__device__ __half g_hk[(size_t)BN*DD];
__device__ __half g_hv[(size_t)BN*DD];
__device__ __half g_hWk[(size_t)DD*DD];
__device__ __half g_hWv[(size_t)DD*DD];
__device__ __half g_Knh[(size_t)BB*HH*NN*DK];
__device__ __half g_Vnh[(size_t)BB*HH*NN*DK];
__device__ float  g_Spart[(size_t)SPLITS*BB*HH*DK*DK];
__device__ __half g_WeffTh[(size_t)BB*DD*DD];
__device__ float  g_beff[(size_t)BB*DD];

// ---------------------------------------------------------------------------
__device__ __forceinline__ uint32_t smem_u32(const void* p) {
    uint32_t a;
    asm("{ .reg .u64 t; cvta.to.shared.u64 t, %1; cvt.u32.u64 %0, t; }"
        : "=r"(a) : "l"(p));
    return a;
}
__device__ __forceinline__ void cp16(uint32_t smem, const void* g) {
    asm volatile("cp.async.cg.shared.global [%0], [%1], 16;"
                 :: "r"(smem), "l"(g));
}
#define CP_COMMIT() asm volatile("cp.async.commit_group;" ::: "memory")
#define CP_WAIT(n)  asm volatile("cp.async.wait_group %0;" :: "n"(n) : "memory")

__device__ __forceinline__ void ldsm4(uint32_t* r, uint32_t a) {
    asm volatile("ldmatrix.sync.aligned.m8n8.x4.shared.b16 {%0,%1,%2,%3}, [%4];"
                 : "=r"(r[0]), "=r"(r[1]), "=r"(r[2]), "=r"(r[3]) : "r"(a));
}
__device__ __forceinline__ void ldsm4t(uint32_t* r, uint32_t a) {
    asm volatile("ldmatrix.sync.aligned.m8n8.x4.trans.shared.b16 {%0,%1,%2,%3}, [%4];"
                 : "=r"(r[0]), "=r"(r[1]), "=r"(r[2]), "=r"(r[3]) : "r"(a));
}
__device__ __forceinline__ void mma16(float* d, const uint32_t* a, const uint32_t* b) {
    asm volatile(
        "mma.sync.aligned.m16n8k16.row.col.f32.f16.f16.f32 "
        "{%0,%1,%2,%3}, {%4,%5,%6,%7}, {%8,%9}, {%0,%1,%2,%3};"
        : "+f"(d[0]), "+f"(d[1]), "+f"(d[2]), "+f"(d[3])
        : "r"(a[0]), "r"(a[1]), "r"(a[2]), "r"(a[3]), "r"(b[0]), "r"(b[1]));
}

// ---------------------------------------------------------------------------
__global__ __launch_bounds__(256)
void f2h3_kernel(const float* __restrict__ a, const float* __restrict__ b,
                 const float* __restrict__ c, int n8)
{
    int i = blockIdx.x * 256 + threadIdx.x;
    int which = i / n8;
    int idx = i - which * n8;
    const float* in = (which == 0) ? a : (which == 1) ? b : c;
    __half* out = (which == 0) ? g_hq : (which == 1) ? g_hk : g_hv;
    float4 x = ((const float4*)in)[2 * idx];
    float4 y = ((const float4*)in)[2 * idx + 1];
    __half2 h[4];
    h[0] = __floats2half2_rn(x.x, x.y);
    h[1] = __floats2half2_rn(x.z, x.w);
    h[2] = __floats2half2_rn(y.x, y.y);
    h[3] = __floats2half2_rn(y.z, y.w);
    ((uint4*)out)[idx] = *(uint4*)h;
}

__global__ __launch_bounds__(256)
void f2h_kernel(const float* __restrict__ in, __half* __restrict__ out, int n8)
{
    int i = blockIdx.x * 256 + threadIdx.x;
    if (i >= n8) return;
    float4 x = ((const float4*)in)[2 * i];
    float4 y = ((const float4*)in)[2 * i + 1];
    __half2 h[4];
    h[0] = __floats2half2_rn(x.x, x.y);
    h[1] = __floats2half2_rn(x.z, x.w);
    h[2] = __floats2half2_rn(y.x, y.y);
    h[3] = __floats2half2_rn(y.z, y.w);
    ((uint4*)out)[i] = *(uint4*)h;
}

// ---------------------------------------------------------------------------
// Big GEMM, fp16 mma.sync: C[128,128] tile of A[BN,1024] @ B^T
// 128 threads, warps 2(M)x2(N), warp tile 64x64 (less LDSM redundancy).
// 3-stage cp.async, ONE sync per chunk; 96KB smem -> 2 CTAs/SM.
// mode 0: B=Wk(h) head jb -> bias+LN -> g_Knh
// mode 1: B=Wv(h) head jb -> bias+LN -> g_Vnh
// mode 2: B=g_WeffTh[b] block jb -> +g_beff -> out (fp32)
// ---------------------------------------------------------------------------
__global__ __launch_bounds__(128)
void gemm_h(const __half* __restrict__ A, const __half* __restrict__ Bmat,
            const float* __restrict__ bias, const float* __restrict__ gamma,
            const float* __restrict__ beta, float* __restrict__ outp, int mode)
{
    extern __shared__ float sm[];
    const int r0  = blockIdx.x * 128;
    const int jb  = blockIdx.y;
    const int b_  = r0 >> 13;
    const int tid = threadIdx.x;
    const int warp = tid >> 5, lane = tid & 31;
    const int wm = warp >> 1, wn = warp & 1;
    const int gid = lane >> 2, tig = lane & 3;

    const __half* Ap = A + (size_t)r0 * DD;
    const __half* Bp = (mode == 2)
        ? (g_WeffTh + (size_t)b_ * DD * DD + (size_t)jb * DK * DD)
        : (Bmat + (size_t)jb * DK * DD);

    const uint32_t smb = smem_u32(sm);

    float acc[4][8][4];
    #pragma unroll
    for (int mt = 0; mt < 4; mt++)
        #pragma unroll
        for (int nt = 0; nt < 8; nt++)
            #pragma unroll
            for (int i = 0; i < 4; i++) acc[mt][nt][i] = 0.f;

    auto load_stage = [&](int kc, int s) {
        uint32_t base = smb + (uint32_t)s * STAGE_B;
        const __half* ga = Ap + kc * 64;
        const __half* gb = Bp + kc * 64;
        #pragma unroll
        for (int u = 0; u < 8; u++) {
            int idx = u * 128 + tid;
            int row = idx >> 3, ch = idx & 7;
            uint32_t off = (uint32_t)(row * 128 + ((ch ^ (row & 7)) << 4));
            cp16(base + off,           ga + (size_t)row * DD + ch * 8);
            cp16(base + 16384u + off,  gb + (size_t)row * DD + ch * 8);
        }
        CP_COMMIT();
    };

    load_stage(0, 0);
    load_stage(1, 1);

    int st = 0;
    for (int kc = 0; kc < NKC; kc++) {
        if (kc < NKC - 1) { CP_WAIT(1); } else { CP_WAIT(0); }
        __syncthreads();
        if (kc + 2 < NKC) {
            int s2 = st + 2; if (s2 >= 3) s2 -= 3;
            load_stage(kc + 2, s2);
        }

        uint32_t ab = smb + (uint32_t)st * STAGE_B;
        uint32_t bb = ab + 16384u;
        #pragma unroll
        for (int ks = 0; ks < 4; ks++) {
            uint32_t afr[4][4];
            #pragma unroll
            for (int mt = 0; mt < 4; mt++) {
                int r = wm * 64 + mt * 16 + (lane & 15);
                int c = ks * 2 + (lane >> 4);
                ldsm4(afr[mt], ab + r * 128 + ((c ^ (r & 7)) << 4));
            }
            #pragma unroll
            for (int eb = 0; eb < 4; eb++) {
                int r = wn * 64 + eb * 16 + ((lane >> 4) << 3) + (lane & 7);
                int c = ks * 2 + ((lane >> 3) & 1);
                uint32_t bfr[4];
                ldsm4(bfr, bb + r * 128 + ((c ^ (r & 7)) << 4));
                #pragma unroll
                for (int mt = 0; mt < 4; mt++) {
                    mma16(acc[mt][eb * 2],     afr[mt], bfr);
                    mma16(acc[mt][eb * 2 + 1], afr[mt], bfr + 2);
                }
            }
        }
        if (++st == 3) st = 0;
    }

    if (mode == 2) {
        float2 bev[8];
        #pragma unroll
        for (int nt = 0; nt < 8; nt++)
            bev[nt] = *(const float2*)&g_beff[(size_t)b_ * DD + jb * DK
                                              + wn * 64 + nt * 8 + tig * 2];
        #pragma unroll
        for (int mt = 0; mt < 4; mt++)
            #pragma unroll
            for (int h = 0; h < 2; h++) {
                int row = wm * 64 + mt * 16 + gid + h * 8;
                float* op = outp + (size_t)(r0 + row) * DD + jb * DK;
                #pragma unroll
                for (int nt = 0; nt < 8; nt++) {
                    float2 o;
                    o.x = acc[mt][nt][2 * h + 0] + bev[nt].x;
                    o.y = acc[mt][nt][2 * h + 1] + bev[nt].y;
                    *(float2*)(op + wn * 64 + nt * 8 + tig * 2) = o;
                }
            }
        return;
    }

    // bias + per-row LN over 128 cols, fp16 out [B,H,N,dk]
    float2 bv[8], gv[8], ev[8];
    #pragma unroll
    for (int nt = 0; nt < 8; nt++) {
        int c = jb * DK + wn * 64 + nt * 8 + tig * 2;
        bv[nt] = *(const float2*)&bias[c];
        gv[nt] = *(const float2*)&gamma[c];
        ev[nt] = *(const float2*)&beta[c];
    }
    float s_[4][2], ss_[4][2];
    #pragma unroll
    for (int mt = 0; mt < 4; mt++)
        #pragma unroll
        for (int h = 0; h < 2; h++) { s_[mt][h] = 0.f; ss_[mt][h] = 0.f; }

    #pragma unroll
    for (int mt = 0; mt < 4; mt++)
        #pragma unroll
        for (int nt = 0; nt < 8; nt++) {
            acc[mt][nt][0] += bv[nt].x; acc[mt][nt][1] += bv[nt].y;
            acc[mt][nt][2] += bv[nt].x; acc[mt][nt][3] += bv[nt].y;
            #pragma unroll
            for (int h = 0; h < 2; h++) {
                float x0 = acc[mt][nt][2 * h], x1 = acc[mt][nt][2 * h + 1];
                s_[mt][h]  += x0 + x1;
                ss_[mt][h] += x0 * x0 + x1 * x1;
            }
        }
    #pragma unroll
    for (int mt = 0; mt < 4; mt++)
        #pragma unroll
        for (int h = 0; h < 2; h++) {
            #pragma unroll
            for (int o = 1; o <= 2; o <<= 1) {
                s_[mt][h]  += __shfl_xor_sync(0xFFFFFFFFu, s_[mt][h],  o);
                ss_[mt][h] += __shfl_xor_sync(0xFFFFFFFFu, ss_[mt][h], o);
            }
        }

    __syncthreads();
    float* red = sm;                 // [128 rows][wn][2]
    if (tig == 0) {
        #pragma unroll
        for (int mt = 0; mt < 4; mt++)
            #pragma unroll
            for (int h = 0; h < 2; h++) {
                int row = wm * 64 + mt * 16 + gid + h * 8;
                red[(row * 2 + wn) * 2 + 0] = s_[mt][h];
                red[(row * 2 + wn) * 2 + 1] = ss_[mt][h];
            }
    }
    __syncthreads();

    __half* dst = mode ? g_Vnh : g_Knh;
    #pragma unroll
    for (int mt = 0; mt < 4; mt++)
        #pragma unroll
        for (int h = 0; h < 2; h++) {
            int row = wm * 64 + mt * 16 + gid + h * 8;
            float st_ = red[(row * 2 + 0) * 2 + 0] + red[(row * 2 + 1) * 2 + 0];
            float sst = red[(row * 2 + 0) * 2 + 1] + red[(row * 2 + 1) * 2 + 1];
            float mean = st_ * (1.f / DK);
            float var  = sst * (1.f / DK) - mean * mean;
            float inv  = rsqrtf(var + EPSF);
            int r  = r0 + row;
            __half* op = dst + (((size_t)(b_ * HH + jb)) * NN + (r & (NN - 1))) * DK;
            #pragma unroll
            for (int nt = 0; nt < 8; nt++) {
                float ox = (acc[mt][nt][2*h+0] - mean) * inv * gv[nt].x + ev[nt].x;
                float oy = (acc[mt][nt][2*h+1] - mean) * inv * gv[nt].y + ev[nt].y;
                *(__half2*)(op + wn * 64 + nt * 8 + tig * 2) = __floats2half2_rn(ox, oy);
            }
        }
}

// ---------------------------------------------------------------------------
// scores on fp16 mma (unchanged)
// ---------------------------------------------------------------------------
__global__ __launch_bounds__(256)
void scores_h()
{
    extern __shared__ float sm[];
    const int split = blockIdx.x;
    const int bh    = blockIdx.y;
    const int tid = threadIdx.x;
    const int warp = tid >> 5, lane = tid & 31;
    const int wm = warp >> 1, wn = warp & 1;
    const int gid = lane >> 2, tig = lane & 3;

    const size_t base = (size_t)bh * NN * DK + (size_t)split * CHS * DK;
    const uint32_t smb = smem_u32(sm);

    float acc[2][8][4];
    #pragma unroll
    for (int mt = 0; mt < 2; mt++)
        #pragma unroll
        for (int nt = 0; nt < 8; nt++)
            #pragma unroll
            for (int i = 0; i < 4; i++) acc[mt][nt][i] = 0.f;

    auto load_stage = [&](int kc, int s) {
        uint32_t kb = smb + (uint32_t)s * 16384u;
        const __half* gk = g_Knh + base + (size_t)kc * 32 * DK;
        const __half* gv = g_Vnh + base + (size_t)kc * 32 * DK;
        #pragma unroll
        for (int u = 0; u < 2; u++) {
            int idx = u * 256 + tid;
            int row = idx >> 4, ch = idx & 15;
            uint32_t off = (uint32_t)(row * 256 + ((ch ^ (row & 7)) << 4));
            cp16(kb + off,          gk + (size_t)row * DK + ch * 8);
            cp16(kb + 8192u + off,  gv + (size_t)row * DK + ch * 8);
        }
        CP_COMMIT();
    };

    const int NCH = CHS / 32;
    load_stage(0, 0);

    for (int kc = 0; kc < NCH; kc++) {
        if (kc + 1 < NCH) { load_stage(kc + 1, (kc + 1) & 1); CP_WAIT(1); }
        else              { CP_WAIT(0); }
        __syncthreads();

        uint32_t kb = smb + (uint32_t)(kc & 1) * 16384u;
        uint32_t vb = kb + 8192u;
        #pragma unroll
        for (int step = 0; step < 2; step++) {
            int n0 = step * 16;
            uint32_t afr[2][4];
            #pragma unroll
            for (int mt = 0; mt < 2; mt++) {
                int m0 = wm * 32 + mt * 16;
                int r = n0 + ((lane >> 4) << 3) + (lane & 7);
                int c = (m0 >> 3) + ((lane >> 3) & 1);
                ldsm4t(afr[mt], kb + r * 256 + ((c ^ (r & 7)) << 4));
            }
            #pragma unroll
            for (int eb = 0; eb < 4; eb++) {
                int e0 = wn * 64 + eb * 16;
                int r = n0 + (((lane >> 3) & 1) << 3) + (lane & 7);
                int c = (e0 >> 3) + (lane >> 4);
                uint32_t bfr[4];
                ldsm4t(bfr, vb + r * 256 + ((c ^ (r & 7)) << 4));
                mma16(acc[0][eb * 2],     afr[0], bfr);
                mma16(acc[0][eb * 2 + 1], afr[0], bfr + 2);
                mma16(acc[1][eb * 2],     afr[1], bfr);
                mma16(acc[1][eb * 2 + 1], afr[1], bfr + 2);
            }
        }
        __syncthreads();
    }

    size_t pbase = ((size_t)split * (BB * HH) + bh) * DK * DK;
    #pragma unroll
    for (int mt = 0; mt < 2; mt++)
        #pragma unroll
        for (int h = 0; h < 2; h++) {
            int row = wm * 32 + mt * 16 + gid + h * 8;
            #pragma unroll
            for (int nt = 0; nt < 8; nt++) {
                float2 o;
                o.x = acc[mt][nt][2 * h + 0];
                o.y = acc[mt][nt][2 * h + 1];
                *(float2*)&g_Spart[pbase + (size_t)row * DK
                                   + wn * 64 + nt * 8 + tig * 2] = o;
            }
        }
}

__global__ void reduce_scores_kernel(float* __restrict__ p_out)
{
    int i = blockIdx.x * 256 + threadIdx.x;
    float s = 0.f;
    #pragma unroll
    for (int sp = 0; sp < SPLITS; sp++)
        s += g_Spart[(size_t)sp * (BB * HH * DK * DK) + i];
    p_out[i] = s * (1.f / NN);
}

__global__ void beff_kernel(const float* __restrict__ bq, const float* __restrict__ p)
{
    int bh = blockIdx.x;
    int e  = threadIdx.x;
    int h  = bh & (HH - 1), b_ = bh >> 3;
    const float* pp = p + (size_t)bh * DK * DK;
    float s = 0.f;
    #pragma unroll 8
    for (int d = 0; d < DK; d++) s += bq[h * DK + d] * pp[(size_t)d * DK + e];
    g_beff[(size_t)b_ * DD + h * DK + e] = s;
}

__global__ __launch_bounds__(256)
void weff_kernel(const float* __restrict__ Wq, const float* __restrict__ p)
{
    const int c0 = blockIdx.x * 64;
    const int bh = blockIdx.y;
    const int h = bh & (HH - 1), b_ = bh >> 3;
    const int tid = threadIdx.x;
    const int ty = tid >> 4, tx = tid & 15;

    __shared__ float As[16][64];
    __shared__ float Bs[16][128];

    float acc[4][8];
    #pragma unroll
    for (int i = 0; i < 4; i++)
        #pragma unroll
        for (int j = 0; j < 8; j++) acc[i][j] = 0.f;

    const int ak = tid >> 4;
    const int ar = (tid & 15) * 4;
    const int bk = tid >> 4;
    const int bc = (tid & 15) * 8;

    for (int k0 = 0; k0 < DK; k0 += 16) {
        *(float4*)&As[ak][ar] =
            *(const float4*)&Wq[(size_t)(h * DK + k0 + ak) * DD + c0 + ar];
        const float* pp = &p[(size_t)bh * DK * DK + (size_t)(k0 + bk) * DK + bc];
        *(float4*)&Bs[bk][bc]     = *(const float4*)pp;
        *(float4*)&Bs[bk][bc + 4] = *(const float4*)(pp + 4);
        __syncthreads();

        #pragma unroll
        for (int kk = 0; kk < 16; kk++) {
            float a[4], b[8];
            *(float4*)a       = *(const float4*)&As[kk][ty * 4];
            *(float4*)b       = *(const float4*)&Bs[kk][tx * 8];
            *(float4*)(b + 4) = *(const float4*)&Bs[kk][tx * 8 + 4];
            #pragma unroll
            for (int i = 0; i < 4; i++)
                #pragma unroll
                for (int j = 0; j < 8; j++) acc[i][j] += a[i] * b[j];
        }
        __syncthreads();
    }

    #pragma unroll
    for (int i = 0; i < 4; i++)
        #pragma unroll
        for (int j = 0; j < 8; j++)
            g_WeffTh[(size_t)b_ * DD * DD
                     + (size_t)(h * DK + tx * 8 + j) * DD + (c0 + ty * 4 + i)]
                = __float2half_rn(acc[i][j]);
}

extern "C" void kernel_launch(void* const* d_in, const int* in_sizes, int n_in,
                              void* d_out, int out_size)
{
    const float* q   = (const float*)d_in[0];
    const float* k   = (const float*)d_in[1];
    const float* v   = (const float*)d_in[2];
    const float* Wq  = (const float*)d_in[3];
    const float* bq  = (const float*)d_in[4];
    const float* Wk  = (const float*)d_in[5];
    const float* bk  = (const float*)d_in[6];
    const float* Wv  = (const float*)d_in[7];
    const float* bv  = (const float*)d_in[8];
    const float* gK  = (const float*)d_in[9];
    const float* beK = (const float*)d_in[10];
    const float* gV  = (const float*)d_in[11];
    const float* beV = (const float*)d_in[12];

    float* out   = (float*)d_out;
    float* p_out = out + (size_t)BN * DD;

    static bool attr_done = false;
    if (!attr_done) {
        cudaFuncSetAttribute(gemm_h, cudaFuncAttributeMaxDynamicSharedMemorySize, GEMM_SMEM);
        cudaFuncSetAttribute(scores_h, cudaFuncAttributeMaxDynamicSharedMemorySize, 32768);
        attr_done = true;
    }

    __half *hq, *hk, *hv, *hWk, *hWv;
    cudaGetSymbolAddress((void**)&hq,  g_hq);
    cudaGetSymbolAddress((void**)&hk,  g_hk);
    cudaGetSymbolAddress((void**)&hv,  g_hv);
    cudaGetSymbolAddress((void**)&hWk, g_hWk);
    cudaGetSymbolAddress((void**)&hWv, g_hWv);

    const int n8_big = (BN * DD) / 8;
    const int n8_w   = (DD * DD) / 8;
    f2h3_kernel<<<(3 * n8_big) / 256, 256>>>(q, k, v, n8_big);
    f2h_kernel<<<(n8_w + 255) / 256, 256>>>(Wk, hWk, n8_w);
    f2h_kernel<<<(n8_w + 255) / 256, 256>>>(Wv, hWv, n8_w);

    dim3 gg(BN / 128, HH);
    gemm_h<<<gg, 128, GEMM_SMEM>>>(hk, hWk, bk, gK, beK, nullptr, 0);
    gemm_h<<<gg, 128, GEMM_SMEM>>>(hv, hWv, bv, gV, beV, nullptr, 1);
    scores_h<<<dim3(SPLITS, BB * HH), 256, 32768>>>();
    reduce_scores_kernel<<<dim3((BB * HH * DK * DK) / 256), 256>>>(p_out);
    beff_kernel<<<dim3(BB * HH), dim3(DK)>>>(bq, p_out);
    weff_kernel<<<dim3(DD / 64, BB * HH), 256>>>(Wq, p_out);
    gemm_h<<<gg, 128, GEMM_SMEM>>>(hq, nullptr, nullptr, nullptr, nullptr, out, 2);
}

// round 8
// speedup vs baseline: 1.1335x; 1.0036x over previous
#include <cuda_runtime.h>
#include <cuda_fp16.h>
#include <cstdint>

#define BB 4
#define NN 8192
#define DD 1024
#define HH 8
#define DK 128
#define BN (BB*NN)
#define SPLITS 8
#define CHS (NN/SPLITS)
#define EPSF 1e-5f
#define NKC (DD/64)            // 16 k-chunks of 64 halves
#define STAGE_B 32768u         // A(16KB)+B(16KB) per stage
#define GEMM_SMEM (3*STAGE_B)  // 98304 -> 2 CTAs/SM

// Scratch (allocation-free device globals)
__device__ __half g_hq[(size_t)BN*DD];
__device__ __half g_hk[(size_t)BN*DD];
__device__ __half g_hv[(size_t)BN*DD];
__device__ __half g_hWk[(size_t)DD*DD];
__device__ __half g_hWv[(size_t)DD*DD];
__device__ __half g_Knh[(size_t)BB*HH*NN*DK];
__device__ __half g_Vnh[(size_t)BB*HH*NN*DK];
__device__ float  g_Spart[(size_t)SPLITS*BB*HH*DK*DK];
__device__ __half g_WeffTh[(size_t)BB*DD*DD];
__device__ float  g_beff[(size_t)BB*DD];

// ---------------------------------------------------------------------------
__device__ __forceinline__ uint32_t smem_u32(const void* p) {
    uint32_t a;
    asm("{ .reg .u64 t; cvta.to.shared.u64 t, %1; cvt.u32.u64 %0, t; }"
        : "=r"(a) : "l"(p));
    return a;
}
__device__ __forceinline__ void cp16(uint32_t smem, const void* g) {
    asm volatile("cp.async.cg.shared.global [%0], [%1], 16;"
                 :: "r"(smem), "l"(g));
}
#define CP_COMMIT() asm volatile("cp.async.commit_group;" ::: "memory")
#define CP_WAIT(n)  asm volatile("cp.async.wait_group %0;" :: "n"(n) : "memory")

__device__ __forceinline__ void ldsm4(uint32_t* r, uint32_t a) {
    asm volatile("ldmatrix.sync.aligned.m8n8.x4.shared.b16 {%0,%1,%2,%3}, [%4];"
                 : "=r"(r[0]), "=r"(r[1]), "=r"(r[2]), "=r"(r[3]) : "r"(a));
}
__device__ __forceinline__ void ldsm4t(uint32_t* r, uint32_t a) {
    asm volatile("ldmatrix.sync.aligned.m8n8.x4.trans.shared.b16 {%0,%1,%2,%3}, [%4];"
                 : "=r"(r[0]), "=r"(r[1]), "=r"(r[2]), "=r"(r[3]) : "r"(a));
}
__device__ __forceinline__ void mma16(float* d, const uint32_t* a, const uint32_t* b) {
    asm volatile(
        "mma.sync.aligned.m16n8k16.row.col.f32.f16.f16.f32 "
        "{%0,%1,%2,%3}, {%4,%5,%6,%7}, {%8,%9}, {%0,%1,%2,%3};"
        : "+f"(d[0]), "+f"(d[1]), "+f"(d[2]), "+f"(d[3])
        : "r"(a[0]), "r"(a[1]), "r"(a[2]), "r"(a[3]), "r"(b[0]), "r"(b[1]));
}

// ---------------------------------------------------------------------------
// converts
// ---------------------------------------------------------------------------
__device__ __forceinline__ void conv8(const float* in, __half* out, int idx) {
    float4 x = ((const float4*)in)[2 * idx];
    float4 y = ((const float4*)in)[2 * idx + 1];
    __half2 h[4];
    h[0] = __floats2half2_rn(x.x, x.y);
    h[1] = __floats2half2_rn(x.z, x.w);
    h[2] = __floats2half2_rn(y.x, y.y);
    h[3] = __floats2half2_rn(y.z, y.w);
    ((uint4*)out)[idx] = *(uint4*)h;
}

__global__ __launch_bounds__(256)
void f2h_kv(const float* __restrict__ k, const float* __restrict__ v, int n8)
{
    int i = blockIdx.x * 256 + threadIdx.x;
    if (i < n8) conv8(k, g_hk, i);
    else        conv8(v, g_hv, i - n8);
}
__global__ __launch_bounds__(256)
void f2h_w(const float* __restrict__ Wk, const float* __restrict__ Wv, int n8)
{
    int i = blockIdx.x * 256 + threadIdx.x;
    if (i < n8) conv8(Wk, g_hWk, i);
    else        conv8(Wv, g_hWv, i - n8);
}
__global__ __launch_bounds__(256)
void f2h_q(const float* __restrict__ q)
{
    int i = blockIdx.x * 256 + threadIdx.x;
    conv8(q, g_hq, i);
}

// ---------------------------------------------------------------------------
// K+V projection GEMM (merged): grid.y 0-7 = K heads, 8-15 = V heads.
// C[128,128] tile of A[BN,1024] @ W^T; epilogue bias+LN -> g_Knh/g_Vnh.
// 128 threads, warps 2x2, warp tile 64x64; 3-stage cp.async, 1 sync/chunk.
// ---------------------------------------------------------------------------
__global__ __launch_bounds__(128)
void gemm_kv(const float* __restrict__ bk, const float* __restrict__ gK,
             const float* __restrict__ beK, const float* __restrict__ bv,
             const float* __restrict__ gV, const float* __restrict__ beV)
{
    extern __shared__ float sm[];
    const int r0  = blockIdx.x * 128;
    const int jb2 = blockIdx.y;
    const int isV = jb2 >> 3;
    const int jb  = jb2 & 7;
    const int b_  = r0 >> 13;
    const int tid = threadIdx.x;
    const int warp = tid >> 5, lane = tid & 31;
    const int wm = warp >> 1, wn = warp & 1;
    const int gid = lane >> 2, tig = lane & 3;

    const __half* Ap = (isV ? g_hv : g_hk) + (size_t)r0 * DD;
    const __half* Bp = (isV ? g_hWv : g_hWk) + (size_t)jb * DK * DD;
    const float* bias  = isV ? bv  : bk;
    const float* gamma = isV ? gV  : gK;
    const float* beta  = isV ? beV : beK;

    const uint32_t smb = smem_u32(sm);

    float acc[4][8][4];
    #pragma unroll
    for (int mt = 0; mt < 4; mt++)
        #pragma unroll
        for (int nt = 0; nt < 8; nt++)
            #pragma unroll
            for (int i = 0; i < 4; i++) acc[mt][nt][i] = 0.f;

    auto load_stage = [&](int kc, int s) {
        uint32_t base = smb + (uint32_t)s * STAGE_B;
        const __half* ga = Ap + kc * 64;
        const __half* gb = Bp + kc * 64;
        #pragma unroll
        for (int u = 0; u < 8; u++) {
            int idx = u * 128 + tid;
            int row = idx >> 3, ch = idx & 7;
            uint32_t off = (uint32_t)(row * 128 + ((ch ^ (row & 7)) << 4));
            cp16(base + off,           ga + (size_t)row * DD + ch * 8);
            cp16(base + 16384u + off,  gb + (size_t)row * DD + ch * 8);
        }
        CP_COMMIT();
    };

    load_stage(0, 0);
    load_stage(1, 1);

    int st = 0;
    for (int kc = 0; kc < NKC; kc++) {
        if (kc < NKC - 1) { CP_WAIT(1); } else { CP_WAIT(0); }
        __syncthreads();
        if (kc + 2 < NKC) {
            int s2 = st + 2; if (s2 >= 3) s2 -= 3;
            load_stage(kc + 2, s2);
        }

        uint32_t ab = smb + (uint32_t)st * STAGE_B;
        uint32_t bb = ab + 16384u;
        #pragma unroll
        for (int ks = 0; ks < 4; ks++) {
            uint32_t afr[4][4];
            #pragma unroll
            for (int mt = 0; mt < 4; mt++) {
                int r = wm * 64 + mt * 16 + (lane & 15);
                int c = ks * 2 + (lane >> 4);
                ldsm4(afr[mt], ab + r * 128 + ((c ^ (r & 7)) << 4));
            }
            #pragma unroll
            for (int eb = 0; eb < 4; eb++) {
                int r = wn * 64 + eb * 16 + ((lane >> 4) << 3) + (lane & 7);
                int c = ks * 2 + ((lane >> 3) & 1);
                uint32_t bfr[4];
                ldsm4(bfr, bb + r * 128 + ((c ^ (r & 7)) << 4));
                #pragma unroll
                for (int mt = 0; mt < 4; mt++) {
                    mma16(acc[mt][eb * 2],     afr[mt], bfr);
                    mma16(acc[mt][eb * 2 + 1], afr[mt], bfr + 2);
                }
            }
        }
        if (++st == 3) st = 0;
    }

    float2 bv_[8], gv_[8], ev_[8];
    #pragma unroll
    for (int nt = 0; nt < 8; nt++) {
        int c = jb * DK + wn * 64 + nt * 8 + tig * 2;
        bv_[nt] = *(const float2*)&bias[c];
        gv_[nt] = *(const float2*)&gamma[c];
        ev_[nt] = *(const float2*)&beta[c];
    }
    float s_[4][2], ss_[4][2];
    #pragma unroll
    for (int mt = 0; mt < 4; mt++)
        #pragma unroll
        for (int h = 0; h < 2; h++) { s_[mt][h] = 0.f; ss_[mt][h] = 0.f; }

    #pragma unroll
    for (int mt = 0; mt < 4; mt++)
        #pragma unroll
        for (int nt = 0; nt < 8; nt++) {
            acc[mt][nt][0] += bv_[nt].x; acc[mt][nt][1] += bv_[nt].y;
            acc[mt][nt][2] += bv_[nt].x; acc[mt][nt][3] += bv_[nt].y;
            #pragma unroll
            for (int h = 0; h < 2; h++) {
                float x0 = acc[mt][nt][2 * h], x1 = acc[mt][nt][2 * h + 1];
                s_[mt][h]  += x0 + x1;
                ss_[mt][h] += x0 * x0 + x1 * x1;
            }
        }
    #pragma unroll
    for (int mt = 0; mt < 4; mt++)
        #pragma unroll
        for (int h = 0; h < 2; h++) {
            #pragma unroll
            for (int o = 1; o <= 2; o <<= 1) {
                s_[mt][h]  += __shfl_xor_sync(0xFFFFFFFFu, s_[mt][h],  o);
                ss_[mt][h] += __shfl_xor_sync(0xFFFFFFFFu, ss_[mt][h], o);
            }
        }

    __syncthreads();
    float* red = sm;
    if (tig == 0) {
        #pragma unroll
        for (int mt = 0; mt < 4; mt++)
            #pragma unroll
            for (int h = 0; h < 2; h++) {
                int row = wm * 64 + mt * 16 + gid + h * 8;
                red[(row * 2 + wn) * 2 + 0] = s_[mt][h];
                red[(row * 2 + wn) * 2 + 1] = ss_[mt][h];
            }
    }
    __syncthreads();

    __half* dst = isV ? g_Vnh : g_Knh;
    #pragma unroll
    for (int mt = 0; mt < 4; mt++)
        #pragma unroll
        for (int h = 0; h < 2; h++) {
            int row = wm * 64 + mt * 16 + gid + h * 8;
            float st_ = red[(row * 2 + 0) * 2 + 0] + red[(row * 2 + 1) * 2 + 0];
            float sst = red[(row * 2 + 0) * 2 + 1] + red[(row * 2 + 1) * 2 + 1];
            float mean = st_ * (1.f / DK);
            float var  = sst * (1.f / DK) - mean * mean;
            float inv  = rsqrtf(var + EPSF);
            int r  = r0 + row;
            __half* op = dst + (((size_t)(b_ * HH + jb)) * NN + (r & (NN - 1))) * DK;
            #pragma unroll
            for (int nt = 0; nt < 8; nt++) {
                float ox = (acc[mt][nt][2*h+0] - mean) * inv * gv_[nt].x + ev_[nt].x;
                float oy = (acc[mt][nt][2*h+1] - mean) * inv * gv_[nt].y + ev_[nt].y;
                *(__half2*)(op + wn * 64 + nt * 8 + tig * 2) = __floats2half2_rn(ox, oy);
            }
        }
}

// ---------------------------------------------------------------------------
// final GEMM: out[r, jb*128..] = g_hq[r,:] @ WeffT[b][jb block]^T + beff
// ---------------------------------------------------------------------------
__global__ __launch_bounds__(128)
void gemm_fin(float* __restrict__ outp)
{
    extern __shared__ float sm[];
    const int r0  = blockIdx.x * 128;
    const int jb  = blockIdx.y;
    const int b_  = r0 >> 13;
    const int tid = threadIdx.x;
    const int warp = tid >> 5, lane = tid & 31;
    const int wm = warp >> 1, wn = warp & 1;
    const int gid = lane >> 2, tig = lane & 3;

    const __half* Ap = g_hq + (size_t)r0 * DD;
    const __half* Bp = g_WeffTh + (size_t)b_ * DD * DD + (size_t)jb * DK * DD;

    const uint32_t smb = smem_u32(sm);

    float acc[4][8][4];
    #pragma unroll
    for (int mt = 0; mt < 4; mt++)
        #pragma unroll
        for (int nt = 0; nt < 8; nt++)
            #pragma unroll
            for (int i = 0; i < 4; i++) acc[mt][nt][i] = 0.f;

    auto load_stage = [&](int kc, int s) {
        uint32_t base = smb + (uint32_t)s * STAGE_B;
        const __half* ga = Ap + kc * 64;
        const __half* gb = Bp + kc * 64;
        #pragma unroll
        for (int u = 0; u < 8; u++) {
            int idx = u * 128 + tid;
            int row = idx >> 3, ch = idx & 7;
            uint32_t off = (uint32_t)(row * 128 + ((ch ^ (row & 7)) << 4));
            cp16(base + off,           ga + (size_t)row * DD + ch * 8);
            cp16(base + 16384u + off,  gb + (size_t)row * DD + ch * 8);
        }
        CP_COMMIT();
    };

    load_stage(0, 0);
    load_stage(1, 1);

    int st = 0;
    for (int kc = 0; kc < NKC; kc++) {
        if (kc < NKC - 1) { CP_WAIT(1); } else { CP_WAIT(0); }
        __syncthreads();
        if (kc + 2 < NKC) {
            int s2 = st + 2; if (s2 >= 3) s2 -= 3;
            load_stage(kc + 2, s2);
        }

        uint32_t ab = smb + (uint32_t)st * STAGE_B;
        uint32_t bb = ab + 16384u;
        #pragma unroll
        for (int ks = 0; ks < 4; ks++) {
            uint32_t afr[4][4];
            #pragma unroll
            for (int mt = 0; mt < 4; mt++) {
                int r = wm * 64 + mt * 16 + (lane & 15);
                int c = ks * 2 + (lane >> 4);
                ldsm4(afr[mt], ab + r * 128 + ((c ^ (r & 7)) << 4));
            }
            #pragma unroll
            for (int eb = 0; eb < 4; eb++) {
                int r = wn * 64 + eb * 16 + ((lane >> 4) << 3) + (lane & 7);
                int c = ks * 2 + ((lane >> 3) & 1);
                uint32_t bfr[4];
                ldsm4(bfr, bb + r * 128 + ((c ^ (r & 7)) << 4));
                #pragma unroll
                for (int mt = 0; mt < 4; mt++) {
                    mma16(acc[mt][eb * 2],     afr[mt], bfr);
                    mma16(acc[mt][eb * 2 + 1], afr[mt], bfr + 2);
                }
            }
        }
        if (++st == 3) st = 0;
    }

    float2 bev[8];
    #pragma unroll
    for (int nt = 0; nt < 8; nt++)
        bev[nt] = *(const float2*)&g_beff[(size_t)b_ * DD + jb * DK
                                          + wn * 64 + nt * 8 + tig * 2];
    #pragma unroll
    for (int mt = 0; mt < 4; mt++)
        #pragma unroll
        for (int h = 0; h < 2; h++) {
            int row = wm * 64 + mt * 16 + gid + h * 8;
            float* op = outp + (size_t)(r0 + row) * DD + jb * DK;
            #pragma unroll
            for (int nt = 0; nt < 8; nt++) {
                float2 o;
                o.x = acc[mt][nt][2 * h + 0] + bev[nt].x;
                o.y = acc[mt][nt][2 * h + 1] + bev[nt].y;
                *(float2*)(op + wn * 64 + nt * 8 + tig * 2) = o;
            }
        }
}

// ---------------------------------------------------------------------------
// scores on fp16 mma (unchanged)
// ---------------------------------------------------------------------------
__global__ __launch_bounds__(256)
void scores_h()
{
    extern __shared__ float sm[];
    const int split = blockIdx.x;
    const int bh    = blockIdx.y;
    const int tid = threadIdx.x;
    const int warp = tid >> 5, lane = tid & 31;
    const int wm = warp >> 1, wn = warp & 1;
    const int gid = lane >> 2, tig = lane & 3;

    const size_t base = (size_t)bh * NN * DK + (size_t)split * CHS * DK;
    const uint32_t smb = smem_u32(sm);

    float acc[2][8][4];
    #pragma unroll
    for (int mt = 0; mt < 2; mt++)
        #pragma unroll
        for (int nt = 0; nt < 8; nt++)
            #pragma unroll
            for (int i = 0; i < 4; i++) acc[mt][nt][i] = 0.f;

    auto load_stage = [&](int kc, int s) {
        uint32_t kb = smb + (uint32_t)s * 16384u;
        const __half* gk = g_Knh + base + (size_t)kc * 32 * DK;
        const __half* gv = g_Vnh + base + (size_t)kc * 32 * DK;
        #pragma unroll
        for (int u = 0; u < 2; u++) {
            int idx = u * 256 + tid;
            int row = idx >> 4, ch = idx & 15;
            uint32_t off = (uint32_t)(row * 256 + ((ch ^ (row & 7)) << 4));
            cp16(kb + off,          gk + (size_t)row * DK + ch * 8);
            cp16(kb + 8192u + off,  gv + (size_t)row * DK + ch * 8);
        }
        CP_COMMIT();
    };

    const int NCH = CHS / 32;
    load_stage(0, 0);

    for (int kc = 0; kc < NCH; kc++) {
        if (kc + 1 < NCH) { load_stage(kc + 1, (kc + 1) & 1); CP_WAIT(1); }
        else              { CP_WAIT(0); }
        __syncthreads();

        uint32_t kb = smb + (uint32_t)(kc & 1) * 16384u;
        uint32_t vb = kb + 8192u;
        #pragma unroll
        for (int step = 0; step < 2; step++) {
            int n0 = step * 16;
            uint32_t afr[2][4];
            #pragma unroll
            for (int mt = 0; mt < 2; mt++) {
                int m0 = wm * 32 + mt * 16;
                int r = n0 + ((lane >> 4) << 3) + (lane & 7);
                int c = (m0 >> 3) + ((lane >> 3) & 1);
                ldsm4t(afr[mt], kb + r * 256 + ((c ^ (r & 7)) << 4));
            }
            #pragma unroll
            for (int eb = 0; eb < 4; eb++) {
                int e0 = wn * 64 + eb * 16;
                int r = n0 + (((lane >> 3) & 1) << 3) + (lane & 7);
                int c = (e0 >> 3) + (lane >> 4);
                uint32_t bfr[4];
                ldsm4t(bfr, vb + r * 256 + ((c ^ (r & 7)) << 4));
                mma16(acc[0][eb * 2],     afr[0], bfr);
                mma16(acc[0][eb * 2 + 1], afr[0], bfr + 2);
                mma16(acc[1][eb * 2],     afr[1], bfr);
                mma16(acc[1][eb * 2 + 1], afr[1], bfr + 2);
            }
        }
        __syncthreads();
    }

    size_t pbase = ((size_t)split * (BB * HH) + bh) * DK * DK;
    #pragma unroll
    for (int mt = 0; mt < 2; mt++)
        #pragma unroll
        for (int h = 0; h < 2; h++) {
            int row = wm * 32 + mt * 16 + gid + h * 8;
            #pragma unroll
            for (int nt = 0; nt < 8; nt++) {
                float2 o;
                o.x = acc[mt][nt][2 * h + 0];
                o.y = acc[mt][nt][2 * h + 1];
                *(float2*)&g_Spart[pbase + (size_t)row * DK
                                   + wn * 64 + nt * 8 + tig * 2] = o;
            }
        }
}

__global__ void reduce_scores_kernel(float* __restrict__ p_out)
{
    int i = blockIdx.x * 256 + threadIdx.x;
    float s = 0.f;
    #pragma unroll
    for (int sp = 0; sp < SPLITS; sp++)
        s += g_Spart[(size_t)sp * (BB * HH * DK * DK) + i];
    p_out[i] = s * (1.f / NN);
}

__global__ void beff_kernel(const float* __restrict__ bq, const float* __restrict__ p)
{
    int bh = blockIdx.x;
    int e  = threadIdx.x;
    int h  = bh & (HH - 1), b_ = bh >> 3;
    const float* pp = p + (size_t)bh * DK * DK;
    float s = 0.f;
    #pragma unroll 8
    for (int d = 0; d < DK; d++) s += bq[h * DK + d] * pp[(size_t)d * DK + e];
    g_beff[(size_t)b_ * DD + h * DK + e] = s;
}

__global__ __launch_bounds__(256)
void weff_kernel(const float* __restrict__ Wq, const float* __restrict__ p)
{
    const int c0 = blockIdx.x * 64;
    const int bh = blockIdx.y;
    const int h = bh & (HH - 1), b_ = bh >> 3;
    const int tid = threadIdx.x;
    const int ty = tid >> 4, tx = tid & 15;

    __shared__ float As[16][64];
    __shared__ float Bs[16][128];

    float acc[4][8];
    #pragma unroll
    for (int i = 0; i < 4; i++)
        #pragma unroll
        for (int j = 0; j < 8; j++) acc[i][j] = 0.f;

    const int ak = tid >> 4;
    const int ar = (tid & 15) * 4;
    const int bk = tid >> 4;
    const int bc = (tid & 15) * 8;

    for (int k0 = 0; k0 < DK; k0 += 16) {
        *(float4*)&As[ak][ar] =
            *(const float4*)&Wq[(size_t)(h * DK + k0 + ak) * DD + c0 + ar];
        const float* pp = &p[(size_t)bh * DK * DK + (size_t)(k0 + bk) * DK + bc];
        *(float4*)&Bs[bk][bc]     = *(const float4*)pp;
        *(float4*)&Bs[bk][bc + 4] = *(const float4*)(pp + 4);
        __syncthreads();

        #pragma unroll
        for (int kk = 0; kk < 16; kk++) {
            float a[4], b[8];
            *(float4*)a       = *(const float4*)&As[kk][ty * 4];
            *(float4*)b       = *(const float4*)&Bs[kk][tx * 8];
            *(float4*)(b + 4) = *(const float4*)&Bs[kk][tx * 8 + 4];
            #pragma unroll
            for (int i = 0; i < 4; i++)
                #pragma unroll
                for (int j = 0; j < 8; j++) acc[i][j] += a[i] * b[j];
        }
        __syncthreads();
    }

    #pragma unroll
    for (int i = 0; i < 4; i++)
        #pragma unroll
        for (int j = 0; j < 8; j++)
            g_WeffTh[(size_t)b_ * DD * DD
                     + (size_t)(h * DK + tx * 8 + j) * DD + (c0 + ty * 4 + i)]
                = __float2half_rn(acc[i][j]);
}

extern "C" void kernel_launch(void* const* d_in, const int* in_sizes, int n_in,
                              void* d_out, int out_size)
{
    const float* q   = (const float*)d_in[0];
    const float* k   = (const float*)d_in[1];
    const float* v   = (const float*)d_in[2];
    const float* Wq  = (const float*)d_in[3];
    const float* bq  = (const float*)d_in[4];
    const float* Wk  = (const float*)d_in[5];
    const float* bk  = (const float*)d_in[6];
    const float* Wv  = (const float*)d_in[7];
    const float* bv  = (const float*)d_in[8];
    const float* gK  = (const float*)d_in[9];
    const float* beK = (const float*)d_in[10];
    const float* gV  = (const float*)d_in[11];
    const float* beV = (const float*)d_in[12];

    float* out   = (float*)d_out;
    float* p_out = out + (size_t)BN * DD;

    static bool init_done = false;
    static cudaStream_t s1;
    static cudaEvent_t ev_fork, ev_q;
    if (!init_done) {
        cudaFuncSetAttribute(gemm_kv,  cudaFuncAttributeMaxDynamicSharedMemorySize, GEMM_SMEM);
        cudaFuncSetAttribute(gemm_fin, cudaFuncAttributeMaxDynamicSharedMemorySize, GEMM_SMEM);
        cudaFuncSetAttribute(scores_h, cudaFuncAttributeMaxDynamicSharedMemorySize, 32768);
        cudaStreamCreateWithFlags(&s1, cudaStreamNonBlocking);
        cudaEventCreateWithFlags(&ev_fork, cudaEventDisableTiming);
        cudaEventCreateWithFlags(&ev_q,    cudaEventDisableTiming);
        init_done = true;
    }

    const int n8_big = (BN * DD) / 8;
    const int n8_w   = (DD * DD) / 8;

    // fork: q-convert runs on s1, hidden under the K/V GEMMs
    cudaEventRecord(ev_fork, 0);
    cudaStreamWaitEvent(s1, ev_fork, 0);
    f2h_q<<<n8_big / 256, 256, 0, s1>>>(q);
    cudaEventRecord(ev_q, s1);

    // main stream
    f2h_kv<<<(2 * n8_big) / 256, 256>>>(k, v, n8_big);
    f2h_w<<<(2 * n8_w) / 256, 256>>>(Wk, Wv, n8_w);
    gemm_kv<<<dim3(BN / 128, 2 * HH), 128, GEMM_SMEM>>>(bk, gK, beK, bv, gV, beV);
    scores_h<<<dim3(SPLITS, BB * HH), 256, 32768>>>();
    reduce_scores_kernel<<<dim3((BB * HH * DK * DK) / 256), 256>>>(p_out);
    beff_kernel<<<dim3(BB * HH), dim3(DK)>>>(bq, p_out);
    weff_kernel<<<dim3(DD / 64, BB * HH), 256>>>(Wq, p_out);
    cudaStreamWaitEvent(0, ev_q, 0);
    gemm_fin<<<dim3(BN / 128, HH), 128, GEMM_SMEM>>>(out);
}

// round 9
// speedup vs baseline: 1.1938x; 1.0532x over previous
#include <cuda_runtime.h>
#include <cuda_fp16.h>
#include <cstdint>

#define BB 4
#define NN 8192
#define DD 1024
#define HH 8
#define DK 128
#define BN (BB*NN)
#define SPLITS 8
#define CHS (NN/SPLITS)
#define EPSF 1e-5f
#define NKC (DD/64)            // 16 k-chunks of 64 elements
// smem: A fp16 2 stages (16KB) + B fp16 3 stages (16KB) = 80KB -> 2 CTAs/SM
#define A_STAGE 16384u
#define B_BASE  32768u
#define GEMM_SMEM 81920

// Scratch (allocation-free device globals)
__device__ __half g_hWk[(size_t)DD*DD];
__device__ __half g_hWv[(size_t)DD*DD];
__device__ __half g_Knh[(size_t)BB*HH*NN*DK];
__device__ __half g_Vnh[(size_t)BB*HH*NN*DK];
__device__ float  g_Spart[(size_t)SPLITS*BB*HH*DK*DK];
__device__ __half g_WeffTh[(size_t)BB*DD*DD];
__device__ float  g_beff[(size_t)BB*DD];

// ---------------------------------------------------------------------------
__device__ __forceinline__ uint32_t smem_u32(const void* p) {
    uint32_t a;
    asm("{ .reg .u64 t; cvta.to.shared.u64 t, %1; cvt.u32.u64 %0, t; }"
        : "=r"(a) : "l"(p));
    return a;
}
__device__ __forceinline__ void cp16(uint32_t smem, const void* g) {
    asm volatile("cp.async.cg.shared.global [%0], [%1], 16;"
                 :: "r"(smem), "l"(g));
}
#define CP_COMMIT() asm volatile("cp.async.commit_group;" ::: "memory")
#define CP_WAIT(n)  asm volatile("cp.async.wait_group %0;" :: "n"(n) : "memory")

__device__ __forceinline__ void ldsm4(uint32_t* r, uint32_t a) {
    asm volatile("ldmatrix.sync.aligned.m8n8.x4.shared.b16 {%0,%1,%2,%3}, [%4];"
                 : "=r"(r[0]), "=r"(r[1]), "=r"(r[2]), "=r"(r[3]) : "r"(a));
}
__device__ __forceinline__ void ldsm4t(uint32_t* r, uint32_t a) {
    asm volatile("ldmatrix.sync.aligned.m8n8.x4.trans.shared.b16 {%0,%1,%2,%3}, [%4];"
                 : "=r"(r[0]), "=r"(r[1]), "=r"(r[2]), "=r"(r[3]) : "r"(a));
}
__device__ __forceinline__ void mma16(float* d, const uint32_t* a, const uint32_t* b) {
    asm volatile(
        "mma.sync.aligned.m16n8k16.row.col.f32.f16.f16.f32 "
        "{%0,%1,%2,%3}, {%4,%5,%6,%7}, {%8,%9}, {%0,%1,%2,%3};"
        : "+f"(d[0]), "+f"(d[1]), "+f"(d[2]), "+f"(d[3])
        : "r"(a[0]), "r"(a[1]), "r"(a[2]), "r"(a[3]), "r"(b[0]), "r"(b[1]));
}
__device__ __forceinline__ uint32_t packh2(float x, float y) {
    uint32_t r;
    asm("cvt.rn.f16x2.f32 %0, %2, %1;" : "=r"(r) : "f"(x), "f"(y));
    return r;
}

// ---------------------------------------------------------------------------
__global__ __launch_bounds__(256)
void f2h_w(const float* __restrict__ Wk, const float* __restrict__ Wv, int n8)
{
    int i = blockIdx.x * 256 + threadIdx.x;
    const float* in = (i < n8) ? Wk : Wv;
    __half* out = (i < n8) ? g_hWk : g_hWv;
    int idx = (i < n8) ? i : i - n8;
    float4 x = ((const float4*)in)[2 * idx];
    float4 y = ((const float4*)in)[2 * idx + 1];
    uint32_t h[4] = { packh2(x.x, x.y), packh2(x.z, x.w),
                      packh2(y.x, y.y), packh2(y.z, y.w) };
    ((uint4*)out)[idx] = *(uint4*)h;
}

// ---------------------------------------------------------------------------
// Fused-convert GEMM core pieces (A fp32 -> registers -> fp16 smem)
// ---------------------------------------------------------------------------
#define LDG_A(areg, Ap, kc) do {                                             \
    _Pragma("unroll")                                                        \
    for (int u = 0; u < 16; u++) {                                           \
        int row = u * 8 + (tid >> 4);                                        \
        (areg)[u] = *(const float4*)((Ap) + (size_t)row * DD + (kc) * 64     \
                                     + (tid & 15) * 4);                      \
    }                                                                        \
} while (0)

#define STS_A(areg, sbase) do {                                              \
    _Pragma("unroll")                                                        \
    for (int u = 0; u < 16; u++) {                                           \
        int row = u * 8 + (tid >> 4);                                        \
        int c4 = tid & 15;                                                   \
        int ch = c4 >> 1;                                                    \
        uint32_t off = (uint32_t)(row * 128 + ((ch ^ (row & 7)) << 4)        \
                                  + (c4 & 1) * 8);                           \
        uint2 hv;                                                            \
        hv.x = packh2((areg)[u].x, (areg)[u].y);                             \
        hv.y = packh2((areg)[u].z, (areg)[u].w);                             \
        *(uint2*)((char*)sm + (sbase) + off) = hv;                           \
    }                                                                        \
} while (0)

#define LD_B(Bp, kc, sbase) do {                                             \
    const __half* gb = (Bp) + (kc) * 64;                                     \
    _Pragma("unroll")                                                        \
    for (int u = 0; u < 8; u++) {                                            \
        int idx = u * 128 + tid;                                             \
        int row = idx >> 3, ch = idx & 7;                                    \
        uint32_t off = (uint32_t)(row * 128 + ((ch ^ (row & 7)) << 4));      \
        cp16(smb + (sbase) + off, gb + (size_t)row * DD + ch * 8);           \
    }                                                                        \
    CP_COMMIT();                                                             \
} while (0)

#define GEMM_MAIN(Ap, Bp)                                                    \
    float4 areg[16];                                                         \
    float acc[4][8][4];                                                      \
    _Pragma("unroll")                                                        \
    for (int mt = 0; mt < 4; mt++)                                           \
        _Pragma("unroll")                                                    \
        for (int nt = 0; nt < 8; nt++)                                       \
            _Pragma("unroll")                                                \
            for (int i = 0; i < 4; i++) acc[mt][nt][i] = 0.f;                \
    LDG_A(areg, Ap, 0);                                                      \
    LD_B(Bp, 0, B_BASE);                                                     \
    LD_B(Bp, 1, B_BASE + A_STAGE);                                           \
    STS_A(areg, 0u);                                                         \
    LDG_A(areg, Ap, 1);                                                      \
    for (int kc = 0; kc < NKC; kc++) {                                       \
        if (kc < NKC - 1) { CP_WAIT(1); } else { CP_WAIT(0); }               \
        __syncthreads();                                                     \
        if (kc + 2 < NKC) {                                                  \
            int s2 = (kc + 2) % 3;                                           \
            LD_B(Bp, kc + 2, B_BASE + (uint32_t)s2 * A_STAGE);               \
        }                                                                    \
        uint32_t ab = smb + (uint32_t)(kc & 1) * A_STAGE;                    \
        uint32_t bb = smb + B_BASE + (uint32_t)(kc % 3) * A_STAGE;           \
        _Pragma("unroll")                                                    \
        for (int ks = 0; ks < 4; ks++) {                                     \
            uint32_t afr[4][4];                                              \
            _Pragma("unroll")                                                \
            for (int mt = 0; mt < 4; mt++) {                                 \
                int r = wm * 64 + mt * 16 + (lane & 15);                     \
                int c = ks * 2 + (lane >> 4);                                \
                ldsm4(afr[mt], ab + r * 128 + ((c ^ (r & 7)) << 4));         \
            }                                                                \
            _Pragma("unroll")                                                \
            for (int eb = 0; eb < 4; eb++) {                                 \
                int r = wn * 64 + eb * 16 + ((lane >> 4) << 3) + (lane & 7); \
                int c = ks * 2 + ((lane >> 3) & 1);                          \
                uint32_t bfr[4];                                             \
                ldsm4(bfr, bb + r * 128 + ((c ^ (r & 7)) << 4));             \
                _Pragma("unroll")                                            \
                for (int mt = 0; mt < 4; mt++) {                             \
                    mma16(acc[mt][eb * 2],     afr[mt], bfr);                \
                    mma16(acc[mt][eb * 2 + 1], afr[mt], bfr + 2);            \
                }                                                            \
            }                                                                \
        }                                                                    \
        if (kc + 1 < NKC) {                                                  \
            STS_A(areg, (uint32_t)((kc + 1) & 1) * A_STAGE);                 \
            if (kc + 2 < NKC) LDG_A(areg, Ap, kc + 2);                       \
        }                                                                    \
    }

// ---------------------------------------------------------------------------
// K+V projection GEMM: grid (16, 256); x: 0-7 K heads, 8-15 V heads.
// A = fp32 k/v input (fused convert); B = fp16 weights.
// ---------------------------------------------------------------------------
__global__ __launch_bounds__(128, 2)
void gemm_kv(const float* __restrict__ kin, const float* __restrict__ vin,
             const float* __restrict__ bk, const float* __restrict__ gK,
             const float* __restrict__ beK, const float* __restrict__ bv,
             const float* __restrict__ gV, const float* __restrict__ beV)
{
    extern __shared__ float sm[];
    const int jb2 = blockIdx.x;
    const int isV = jb2 >> 3;
    const int jb  = jb2 & 7;
    const int r0  = blockIdx.y * 128;
    const int b_  = r0 >> 13;
    const int tid = threadIdx.x;
    const int warp = tid >> 5, lane = tid & 31;
    const int wm = warp >> 1, wn = warp & 1;
    const int gid = lane >> 2, tig = lane & 3;

    const float* Ap = (isV ? vin : kin) + (size_t)r0 * DD;
    const __half* Bp = (isV ? g_hWv : g_hWk) + (size_t)jb * DK * DD;
    const float* bias  = isV ? bv  : bk;
    const float* gamma = isV ? gV  : gK;
    const float* beta  = isV ? beV : beK;
    const uint32_t smb = smem_u32(sm);

    GEMM_MAIN(Ap, Bp)

    // epilogue: bias + per-row LN over 128 cols, fp16 out [B,H,N,dk]
    float2 bv_[8], gv_[8], ev_[8];
    #pragma unroll
    for (int nt = 0; nt < 8; nt++) {
        int c = jb * DK + wn * 64 + nt * 8 + tig * 2;
        bv_[nt] = *(const float2*)&bias[c];
        gv_[nt] = *(const float2*)&gamma[c];
        ev_[nt] = *(const float2*)&beta[c];
    }
    float s_[4][2], ss_[4][2];
    #pragma unroll
    for (int mt = 0; mt < 4; mt++)
        #pragma unroll
        for (int h = 0; h < 2; h++) { s_[mt][h] = 0.f; ss_[mt][h] = 0.f; }

    #pragma unroll
    for (int mt = 0; mt < 4; mt++)
        #pragma unroll
        for (int nt = 0; nt < 8; nt++) {
            acc[mt][nt][0] += bv_[nt].x; acc[mt][nt][1] += bv_[nt].y;
            acc[mt][nt][2] += bv_[nt].x; acc[mt][nt][3] += bv_[nt].y;
            #pragma unroll
            for (int h = 0; h < 2; h++) {
                float x0 = acc[mt][nt][2 * h], x1 = acc[mt][nt][2 * h + 1];
                s_[mt][h]  += x0 + x1;
                ss_[mt][h] += x0 * x0 + x1 * x1;
            }
        }
    #pragma unroll
    for (int mt = 0; mt < 4; mt++)
        #pragma unroll
        for (int h = 0; h < 2; h++) {
            #pragma unroll
            for (int o = 1; o <= 2; o <<= 1) {
                s_[mt][h]  += __shfl_xor_sync(0xFFFFFFFFu, s_[mt][h],  o);
                ss_[mt][h] += __shfl_xor_sync(0xFFFFFFFFu, ss_[mt][h], o);
            }
        }

    __syncthreads();
    float* red = sm;
    if (tig == 0) {
        #pragma unroll
        for (int mt = 0; mt < 4; mt++)
            #pragma unroll
            for (int h = 0; h < 2; h++) {
                int row = wm * 64 + mt * 16 + gid + h * 8;
                red[(row * 2 + wn) * 2 + 0] = s_[mt][h];
                red[(row * 2 + wn) * 2 + 1] = ss_[mt][h];
            }
    }
    __syncthreads();

    __half* dst = isV ? g_Vnh : g_Knh;
    #pragma unroll
    for (int mt = 0; mt < 4; mt++)
        #pragma unroll
        for (int h = 0; h < 2; h++) {
            int row = wm * 64 + mt * 16 + gid + h * 8;
            float st_ = red[(row * 2 + 0) * 2 + 0] + red[(row * 2 + 1) * 2 + 0];
            float sst = red[(row * 2 + 0) * 2 + 1] + red[(row * 2 + 1) * 2 + 1];
            float mean = st_ * (1.f / DK);
            float var  = sst * (1.f / DK) - mean * mean;
            float inv  = rsqrtf(var + EPSF);
            int r  = r0 + row;
            __half* op = dst + (((size_t)(b_ * HH + jb)) * NN + (r & (NN - 1))) * DK;
            #pragma unroll
            for (int nt = 0; nt < 8; nt++) {
                float ox = (acc[mt][nt][2*h+0] - mean) * inv * gv_[nt].x + ev_[nt].x;
                float oy = (acc[mt][nt][2*h+1] - mean) * inv * gv_[nt].y + ev_[nt].y;
                *(__half2*)(op + wn * 64 + nt * 8 + tig * 2)
                    = *(__half2*)&(uint32_t&)(const uint32_t&)packh2(ox, oy);
            }
        }
}

// ---------------------------------------------------------------------------
// final GEMM: grid (8, 256); A = fp32 q (fused convert), B = WeffTh fp16.
// ---------------------------------------------------------------------------
__global__ __launch_bounds__(128, 2)
void gemm_fin(const float* __restrict__ qin, float* __restrict__ outp)
{
    extern __shared__ float sm[];
    const int jb  = blockIdx.x;
    const int r0  = blockIdx.y * 128;
    const int b_  = r0 >> 13;
    const int tid = threadIdx.x;
    const int warp = tid >> 5, lane = tid & 31;
    const int wm = warp >> 1, wn = warp & 1;
    const int gid = lane >> 2, tig = lane & 3;

    const float* Ap = qin + (size_t)r0 * DD;
    const __half* Bp = g_WeffTh + (size_t)b_ * DD * DD + (size_t)jb * DK * DD;
    const uint32_t smb = smem_u32(sm);

    GEMM_MAIN(Ap, Bp)

    float2 bev[8];
    #pragma unroll
    for (int nt = 0; nt < 8; nt++)
        bev[nt] = *(const float2*)&g_beff[(size_t)b_ * DD + jb * DK
                                          + wn * 64 + nt * 8 + tig * 2];
    #pragma unroll
    for (int mt = 0; mt < 4; mt++)
        #pragma unroll
        for (int h = 0; h < 2; h++) {
            int row = wm * 64 + mt * 16 + gid + h * 8;
            float* op = outp + (size_t)(r0 + row) * DD + jb * DK;
            #pragma unroll
            for (int nt = 0; nt < 8; nt++) {
                float2 o;
                o.x = acc[mt][nt][2 * h + 0] + bev[nt].x;
                o.y = acc[mt][nt][2 * h + 1] + bev[nt].y;
                *(float2*)(op + wn * 64 + nt * 8 + tig * 2) = o;
            }
        }
}

// ---------------------------------------------------------------------------
// scores on fp16 mma (unchanged)
// ---------------------------------------------------------------------------
__global__ __launch_bounds__(256)
void scores_h()
{
    extern __shared__ float sm[];
    const int split = blockIdx.x;
    const int bh    = blockIdx.y;
    const int tid = threadIdx.x;
    const int warp = tid >> 5, lane = tid & 31;
    const int wm = warp >> 1, wn = warp & 1;
    const int gid = lane >> 2, tig = lane & 3;

    const size_t base = (size_t)bh * NN * DK + (size_t)split * CHS * DK;
    const uint32_t smb = smem_u32(sm);

    float acc[2][8][4];
    #pragma unroll
    for (int mt = 0; mt < 2; mt++)
        #pragma unroll
        for (int nt = 0; nt < 8; nt++)
            #pragma unroll
            for (int i = 0; i < 4; i++) acc[mt][nt][i] = 0.f;

    auto load_stage = [&](int kc, int s) {
        uint32_t kb = smb + (uint32_t)s * 16384u;
        const __half* gk = g_Knh + base + (size_t)kc * 32 * DK;
        const __half* gv = g_Vnh + base + (size_t)kc * 32 * DK;
        #pragma unroll
        for (int u = 0; u < 2; u++) {
            int idx = u * 256 + tid;
            int row = idx >> 4, ch = idx & 15;
            uint32_t off = (uint32_t)(row * 256 + ((ch ^ (row & 7)) << 4));
            cp16(kb + off,          gk + (size_t)row * DK + ch * 8);
            cp16(kb + 8192u + off,  gv + (size_t)row * DK + ch * 8);
        }
        CP_COMMIT();
    };

    const int NCH = CHS / 32;
    load_stage(0, 0);

    for (int kc = 0; kc < NCH; kc++) {
        if (kc + 1 < NCH) { load_stage(kc + 1, (kc + 1) & 1); CP_WAIT(1); }
        else              { CP_WAIT(0); }
        __syncthreads();

        uint32_t kb = smb + (uint32_t)(kc & 1) * 16384u;
        uint32_t vb = kb + 8192u;
        #pragma unroll
        for (int step = 0; step < 2; step++) {
            int n0 = step * 16;
            uint32_t afr[2][4];
            #pragma unroll
            for (int mt = 0; mt < 2; mt++) {
                int m0 = wm * 32 + mt * 16;
                int r = n0 + ((lane >> 4) << 3) + (lane & 7);
                int c = (m0 >> 3) + ((lane >> 3) & 1);
                ldsm4t(afr[mt], kb + r * 256 + ((c ^ (r & 7)) << 4));
            }
            #pragma unroll
            for (int eb = 0; eb < 4; eb++) {
                int e0 = wn * 64 + eb * 16;
                int r = n0 + (((lane >> 3) & 1) << 3) + (lane & 7);
                int c = (e0 >> 3) + (lane >> 4);
                uint32_t bfr[4];
                ldsm4t(bfr, vb + r * 256 + ((c ^ (r & 7)) << 4));
                mma16(acc[0][eb * 2],     afr[0], bfr);
                mma16(acc[0][eb * 2 + 1], afr[0], bfr + 2);
                mma16(acc[1][eb * 2],     afr[1], bfr);
                mma16(acc[1][eb * 2 + 1], afr[1], bfr + 2);
            }
        }
        __syncthreads();
    }

    size_t pbase = ((size_t)split * (BB * HH) + bh) * DK * DK;
    #pragma unroll
    for (int mt = 0; mt < 2; mt++)
        #pragma unroll
        for (int h = 0; h < 2; h++) {
            int row = wm * 32 + mt * 16 + gid + h * 8;
            #pragma unroll
            for (int nt = 0; nt < 8; nt++) {
                float2 o;
                o.x = acc[mt][nt][2 * h + 0];
                o.y = acc[mt][nt][2 * h + 1];
                *(float2*)&g_Spart[pbase + (size_t)row * DK
                                   + wn * 64 + nt * 8 + tig * 2] = o;
            }
        }
}

__global__ void reduce_scores_kernel(float* __restrict__ p_out)
{
    int i = blockIdx.x * 256 + threadIdx.x;
    float s = 0.f;
    #pragma unroll
    for (int sp = 0; sp < SPLITS; sp++)
        s += g_Spart[(size_t)sp * (BB * HH * DK * DK) + i];
    p_out[i] = s * (1.f / NN);
}

__global__ void beff_kernel(const float* __restrict__ bq, const float* __restrict__ p)
{
    int bh = blockIdx.x;
    int e  = threadIdx.x;
    int h  = bh & (HH - 1), b_ = bh >> 3;
    const float* pp = p + (size_t)bh * DK * DK;
    float s = 0.f;
    #pragma unroll 8
    for (int d = 0; d < DK; d++) s += bq[h * DK + d] * pp[(size_t)d * DK + e];
    g_beff[(size_t)b_ * DD + h * DK + e] = s;
}

__global__ __launch_bounds__(256)
void weff_kernel(const float* __restrict__ Wq, const float* __restrict__ p)
{
    const int c0 = blockIdx.x * 64;
    const int bh = blockIdx.y;
    const int h = bh & (HH - 1), b_ = bh >> 3;
    const int tid = threadIdx.x;
    const int ty = tid >> 4, tx = tid & 15;

    __shared__ float As[16][64];
    __shared__ float Bs[16][128];

    float acc[4][8];
    #pragma unroll
    for (int i = 0; i < 4; i++)
        #pragma unroll
        for (int j = 0; j < 8; j++) acc[i][j] = 0.f;

    const int ak = tid >> 4;
    const int ar = (tid & 15) * 4;
    const int bk = tid >> 4;
    const int bc = (tid & 15) * 8;

    for (int k0 = 0; k0 < DK; k0 += 16) {
        *(float4*)&As[ak][ar] =
            *(const float4*)&Wq[(size_t)(h * DK + k0 + ak) * DD + c0 + ar];
        const float* pp = &p[(size_t)bh * DK * DK + (size_t)(k0 + bk) * DK + bc];
        *(float4*)&Bs[bk][bc]     = *(const float4*)pp;
        *(float4*)&Bs[bk][bc + 4] = *(const float4*)(pp + 4);
        __syncthreads();

        #pragma unroll
        for (int kk = 0; kk < 16; kk++) {
            float a[4], b[8];
            *(float4*)a       = *(const float4*)&As[kk][ty * 4];
            *(float4*)b       = *(const float4*)&Bs[kk][tx * 8];
            *(float4*)(b + 4) = *(const float4*)&Bs[kk][tx * 8 + 4];
            #pragma unroll
            for (int i = 0; i < 4; i++)
                #pragma unroll
                for (int j = 0; j < 8; j++) acc[i][j] += a[i] * b[j];
        }
        __syncthreads();
    }

    #pragma unroll
    for (int i = 0; i < 4; i++)
        #pragma unroll
        for (int j = 0; j < 8; j++)
            g_WeffTh[(size_t)b_ * DD * DD
                     + (size_t)(h * DK + tx * 8 + j) * DD + (c0 + ty * 4 + i)]
                = __float2half_rn(acc[i][j]);
}

extern "C" void kernel_launch(void* const* d_in, const int* in_sizes, int n_in,
                              void* d_out, int out_size)
{
    const float* q   = (const float*)d_in[0];
    const float* k   = (const float*)d_in[1];
    const float* v   = (const float*)d_in[2];
    const float* Wq  = (const float*)d_in[3];
    const float* bq  = (const float*)d_in[4];
    const float* Wk  = (const float*)d_in[5];
    const float* bk  = (const float*)d_in[6];
    const float* Wv  = (const float*)d_in[7];
    const float* bv  = (const float*)d_in[8];
    const float* gK  = (const float*)d_in[9];
    const float* beK = (const float*)d_in[10];
    const float* gV  = (const float*)d_in[11];
    const float* beV = (const float*)d_in[12];

    float* out   = (float*)d_out;
    float* p_out = out + (size_t)BN * DD;

    static bool init_done = false;
    if (!init_done) {
        cudaFuncSetAttribute(gemm_kv,  cudaFuncAttributeMaxDynamicSharedMemorySize, GEMM_SMEM);
        cudaFuncSetAttribute(gemm_fin, cudaFuncAttributeMaxDynamicSharedMemorySize, GEMM_SMEM);
        cudaFuncSetAttribute(scores_h, cudaFuncAttributeMaxDynamicSharedMemorySize, 32768);
        init_done = true;
    }

    const int n8_w = (DD * DD) / 8;
    f2h_w<<<(2 * n8_w) / 256, 256>>>(Wk, Wv, n8_w);

    gemm_kv<<<dim3(2 * HH, BN / 128), 128, GEMM_SMEM>>>(k, v, bk, gK, beK, bv, gV, beV);
    scores_h<<<dim3(SPLITS, BB * HH), 256, 32768>>>();
    reduce_scores_kernel<<<dim3((BB * HH * DK * DK) / 256), 256>>>(p_out);
    beff_kernel<<<dim3(BB * HH), dim3(DK)>>>(bq, p_out);
    weff_kernel<<<dim3(DD / 64, BB * HH), 256>>>(Wq, p_out);
    gemm_fin<<<dim3(HH, BN / 128), 128, GEMM_SMEM>>>(q, out);
}

// round 10
// speedup vs baseline: 1.2026x; 1.0074x over previous
#include <cuda_runtime.h>
#include <cuda_fp16.h>
#include <cstdint>

#define BB 4
#define NN 8192
#define DD 1024
#define HH 8
#define DK 128
#define BN (BB*NN)
#define SPLITS 16
#define CHS (NN/SPLITS)        // 512 rows per scores split
#define EPSF 1e-5f
#define NKC (DD/64)            // 16 k-chunks of 64 elements
// gemm smem: A fp16 2 stages + B fp16 3 stages, 16KB each = 80KB -> 2 CTAs/SM
#define A_STAGE 16384u
#define B_BASE  32768u
#define GEMM_SMEM 81920
#define SC_SMEM  49152         // scores: 3 stages x (K 8KB + V 8KB)

// Scratch (allocation-free device globals)
__device__ __half g_hWk[(size_t)DD*DD];
__device__ __half g_hWv[(size_t)DD*DD];
__device__ __half g_Knh[(size_t)BB*HH*NN*DK];
__device__ __half g_Vnh[(size_t)BB*HH*NN*DK];
__device__ float  g_Spart[(size_t)SPLITS*BB*HH*DK*DK];
__device__ __half g_WeffTh[(size_t)BB*DD*DD];
__device__ float  g_beff[(size_t)BB*DD];

// ---------------------------------------------------------------------------
__device__ __forceinline__ uint32_t smem_u32(const void* p) {
    uint32_t a;
    asm("{ .reg .u64 t; cvta.to.shared.u64 t, %1; cvt.u32.u64 %0, t; }"
        : "=r"(a) : "l"(p));
    return a;
}
__device__ __forceinline__ void cp16(uint32_t smem, const void* g) {
    asm volatile("cp.async.cg.shared.global [%0], [%1], 16;"
                 :: "r"(smem), "l"(g));
}
#define CP_COMMIT() asm volatile("cp.async.commit_group;" ::: "memory")
#define CP_WAIT(n)  asm volatile("cp.async.wait_group %0;" :: "n"(n) : "memory")

__device__ __forceinline__ void ldsm4(uint32_t* r, uint32_t a) {
    asm volatile("ldmatrix.sync.aligned.m8n8.x4.shared.b16 {%0,%1,%2,%3}, [%4];"
                 : "=r"(r[0]), "=r"(r[1]), "=r"(r[2]), "=r"(r[3]) : "r"(a));
}
__device__ __forceinline__ void ldsm4t(uint32_t* r, uint32_t a) {
    asm volatile("ldmatrix.sync.aligned.m8n8.x4.trans.shared.b16 {%0,%1,%2,%3}, [%4];"
                 : "=r"(r[0]), "=r"(r[1]), "=r"(r[2]), "=r"(r[3]) : "r"(a));
}
__device__ __forceinline__ void mma16(float* d, const uint32_t* a, const uint32_t* b) {
    asm volatile(
        "mma.sync.aligned.m16n8k16.row.col.f32.f16.f16.f32 "
        "{%0,%1,%2,%3}, {%4,%5,%6,%7}, {%8,%9}, {%0,%1,%2,%3};"
        : "+f"(d[0]), "+f"(d[1]), "+f"(d[2]), "+f"(d[3])
        : "r"(a[0]), "r"(a[1]), "r"(a[2]), "r"(a[3]), "r"(b[0]), "r"(b[1]));
}
__device__ __forceinline__ uint32_t packh2(float x, float y) {
    uint32_t r;
    asm("cvt.rn.f16x2.f32 %0, %2, %1;" : "=r"(r) : "f"(x), "f"(y));
    return r;
}

// ---------------------------------------------------------------------------
__global__ __launch_bounds__(256)
void f2h_w(const float* __restrict__ Wk, const float* __restrict__ Wv, int n8)
{
    int i = blockIdx.x * 256 + threadIdx.x;
    const float* in = (i < n8) ? Wk : Wv;
    __half* out = (i < n8) ? g_hWk : g_hWv;
    int idx = (i < n8) ? i : i - n8;
    float4 x = ((const float4*)in)[2 * idx];
    float4 y = ((const float4*)in)[2 * idx + 1];
    uint32_t h[4] = { packh2(x.x, x.y), packh2(x.z, x.w),
                      packh2(y.x, y.y), packh2(y.z, y.w) };
    ((uint4*)out)[idx] = *(uint4*)h;
}

// ---------------------------------------------------------------------------
// Fused-convert GEMM core (A fp32 -> regs -> fp16 smem; B fp16 cp.async)
// ---------------------------------------------------------------------------
#define LDG_A(areg, Ap, kc) do {                                             \
    _Pragma("unroll")                                                        \
    for (int u = 0; u < 16; u++) {                                           \
        int row = u * 8 + (tid >> 4);                                        \
        (areg)[u] = *(const float4*)((Ap) + (size_t)row * DD + (kc) * 64     \
                                     + (tid & 15) * 4);                      \
    }                                                                        \
} while (0)

#define STS_A(areg, sbase) do {                                              \
    _Pragma("unroll")                                                        \
    for (int u = 0; u < 16; u++) {                                           \
        int row = u * 8 + (tid >> 4);                                        \
        int c4 = tid & 15;                                                   \
        int ch = c4 >> 1;                                                    \
        uint32_t off = (uint32_t)(row * 128 + ((ch ^ (row & 7)) << 4)        \
                                  + (c4 & 1) * 8);                           \
        uint2 hv;                                                            \
        hv.x = packh2((areg)[u].x, (areg)[u].y);                             \
        hv.y = packh2((areg)[u].z, (areg)[u].w);                             \
        *(uint2*)((char*)sm + (sbase) + off) = hv;                           \
    }                                                                        \
} while (0)

#define LD_B(Bp, kc, sbase) do {                                             \
    const __half* gb = (Bp) + (kc) * 64;                                     \
    _Pragma("unroll")                                                        \
    for (int u = 0; u < 8; u++) {                                            \
        int idx = u * 128 + tid;                                             \
        int row = idx >> 3, ch = idx & 7;                                    \
        uint32_t off = (uint32_t)(row * 128 + ((ch ^ (row & 7)) << 4));      \
        cp16(smb + (sbase) + off, gb + (size_t)row * DD + ch * 8);           \
    }                                                                        \
    CP_COMMIT();                                                             \
} while (0)

#define GEMM_MAIN(Ap, Bp)                                                    \
    float4 areg[16];                                                         \
    float acc[4][8][4];                                                      \
    _Pragma("unroll")                                                        \
    for (int mt = 0; mt < 4; mt++)                                           \
        _Pragma("unroll")                                                    \
        for (int nt = 0; nt < 8; nt++)                                       \
            _Pragma("unroll")                                                \
            for (int i = 0; i < 4; i++) acc[mt][nt][i] = 0.f;                \
    LDG_A(areg, Ap, 0);                                                      \
    LD_B(Bp, 0, B_BASE);                                                     \
    LD_B(Bp, 1, B_BASE + A_STAGE);                                           \
    STS_A(areg, 0u);                                                         \
    LDG_A(areg, Ap, 1);                                                      \
    for (int kc = 0; kc < NKC; kc++) {                                       \
        if (kc < NKC - 1) { CP_WAIT(1); } else { CP_WAIT(0); }               \
        __syncthreads();                                                     \
        if (kc + 2 < NKC) {                                                  \
            int s2 = (kc + 2) % 3;                                           \
            LD_B(Bp, kc + 2, B_BASE + (uint32_t)s2 * A_STAGE);               \
        }                                                                    \
        uint32_t ab = smb + (uint32_t)(kc & 1) * A_STAGE;                    \
        uint32_t bb = smb + B_BASE + (uint32_t)(kc % 3) * A_STAGE;           \
        _Pragma("unroll")                                                    \
        for (int ks = 0; ks < 4; ks++) {                                     \
            uint32_t afr[4][4];                                              \
            _Pragma("unroll")                                                \
            for (int mt = 0; mt < 4; mt++) {                                 \
                int r = wm * 64 + mt * 16 + (lane & 15);                     \
                int c = ks * 2 + (lane >> 4);                                \
                ldsm4(afr[mt], ab + r * 128 + ((c ^ (r & 7)) << 4));         \
            }                                                                \
            _Pragma("unroll")                                                \
            for (int eb = 0; eb < 4; eb++) {                                 \
                int r = wn * 64 + eb * 16 + ((lane >> 4) << 3) + (lane & 7); \
                int c = ks * 2 + ((lane >> 3) & 1);                          \
                uint32_t bfr[4];                                             \
                ldsm4(bfr, bb + r * 128 + ((c ^ (r & 7)) << 4));             \
                _Pragma("unroll")                                            \
                for (int mt = 0; mt < 4; mt++) {                             \
                    mma16(acc[mt][eb * 2],     afr[mt], bfr);                \
                    mma16(acc[mt][eb * 2 + 1], afr[mt], bfr + 2);            \
                }                                                            \
            }                                                                \
        }                                                                    \
        if (kc + 1 < NKC) {                                                  \
            STS_A(areg, (uint32_t)((kc + 1) & 1) * A_STAGE);                 \
            if (kc + 2 < NKC) LDG_A(areg, Ap, kc + 2);                       \
        }                                                                    \
    }

// ---------------------------------------------------------------------------
// K+V projection GEMM: grid (16, 256); x: 0-7 K heads, 8-15 V heads.
// ---------------------------------------------------------------------------
__global__ __launch_bounds__(128, 2)
void gemm_kv(const float* __restrict__ kin, const float* __restrict__ vin,
             const float* __restrict__ bk, const float* __restrict__ gK,
             const float* __restrict__ beK, const float* __restrict__ bv,
             const float* __restrict__ gV, const float* __restrict__ beV)
{
    extern __shared__ float sm[];
    const int jb2 = blockIdx.x;
    const int isV = jb2 >> 3;
    const int jb  = jb2 & 7;
    const int r0  = blockIdx.y * 128;
    const int b_  = r0 >> 13;
    const int tid = threadIdx.x;
    const int warp = tid >> 5, lane = tid & 31;
    const int wm = warp >> 1, wn = warp & 1;
    const int gid = lane >> 2, tig = lane & 3;

    const float* Ap = (isV ? vin : kin) + (size_t)r0 * DD;
    const __half* Bp = (isV ? g_hWv : g_hWk) + (size_t)jb * DK * DD;
    const float* bias  = isV ? bv  : bk;
    const float* gamma = isV ? gV  : gK;
    const float* beta  = isV ? beV : beK;
    const uint32_t smb = smem_u32(sm);

    GEMM_MAIN(Ap, Bp)

    float2 bv_[8], gv_[8], ev_[8];
    #pragma unroll
    for (int nt = 0; nt < 8; nt++) {
        int c = jb * DK + wn * 64 + nt * 8 + tig * 2;
        bv_[nt] = *(const float2*)&bias[c];
        gv_[nt] = *(const float2*)&gamma[c];
        ev_[nt] = *(const float2*)&beta[c];
    }
    float s_[4][2], ss_[4][2];
    #pragma unroll
    for (int mt = 0; mt < 4; mt++)
        #pragma unroll
        for (int h = 0; h < 2; h++) { s_[mt][h] = 0.f; ss_[mt][h] = 0.f; }

    #pragma unroll
    for (int mt = 0; mt < 4; mt++)
        #pragma unroll
        for (int nt = 0; nt < 8; nt++) {
            acc[mt][nt][0] += bv_[nt].x; acc[mt][nt][1] += bv_[nt].y;
            acc[mt][nt][2] += bv_[nt].x; acc[mt][nt][3] += bv_[nt].y;
            #pragma unroll
            for (int h = 0; h < 2; h++) {
                float x0 = acc[mt][nt][2 * h], x1 = acc[mt][nt][2 * h + 1];
                s_[mt][h]  += x0 + x1;
                ss_[mt][h] += x0 * x0 + x1 * x1;
            }
        }
    #pragma unroll
    for (int mt = 0; mt < 4; mt++)
        #pragma unroll
        for (int h = 0; h < 2; h++) {
            #pragma unroll
            for (int o = 1; o <= 2; o <<= 1) {
                s_[mt][h]  += __shfl_xor_sync(0xFFFFFFFFu, s_[mt][h],  o);
                ss_[mt][h] += __shfl_xor_sync(0xFFFFFFFFu, ss_[mt][h], o);
            }
        }

    __syncthreads();
    float* red = sm;
    if (tig == 0) {
        #pragma unroll
        for (int mt = 0; mt < 4; mt++)
            #pragma unroll
            for (int h = 0; h < 2; h++) {
                int row = wm * 64 + mt * 16 + gid + h * 8;
                red[(row * 2 + wn) * 2 + 0] = s_[mt][h];
                red[(row * 2 + wn) * 2 + 1] = ss_[mt][h];
            }
    }
    __syncthreads();

    __half* dst = isV ? g_Vnh : g_Knh;
    #pragma unroll
    for (int mt = 0; mt < 4; mt++)
        #pragma unroll
        for (int h = 0; h < 2; h++) {
            int row = wm * 64 + mt * 16 + gid + h * 8;
            float st_ = red[(row * 2 + 0) * 2 + 0] + red[(row * 2 + 1) * 2 + 0];
            float sst = red[(row * 2 + 0) * 2 + 1] + red[(row * 2 + 1) * 2 + 1];
            float mean = st_ * (1.f / DK);
            float var  = sst * (1.f / DK) - mean * mean;
            float inv  = rsqrtf(var + EPSF);
            int r  = r0 + row;
            __half* op = dst + (((size_t)(b_ * HH + jb)) * NN + (r & (NN - 1))) * DK;
            #pragma unroll
            for (int nt = 0; nt < 8; nt++) {
                float ox = (acc[mt][nt][2*h+0] - mean) * inv * gv_[nt].x + ev_[nt].x;
                float oy = (acc[mt][nt][2*h+1] - mean) * inv * gv_[nt].y + ev_[nt].y;
                uint32_t pk = packh2(ox, oy);
                *(uint32_t*)(op + wn * 64 + nt * 8 + tig * 2) = pk;
            }
        }
}

// ---------------------------------------------------------------------------
// final GEMM: grid (8, 256); A = fp32 q (fused convert), B = WeffTh fp16.
// ---------------------------------------------------------------------------
__global__ __launch_bounds__(128, 2)
void gemm_fin(const float* __restrict__ qin, float* __restrict__ outp)
{
    extern __shared__ float sm[];
    const int jb  = blockIdx.x;
    const int r0  = blockIdx.y * 128;
    const int b_  = r0 >> 13;
    const int tid = threadIdx.x;
    const int warp = tid >> 5, lane = tid & 31;
    const int wm = warp >> 1, wn = warp & 1;
    const int gid = lane >> 2, tig = lane & 3;

    const float* Ap = qin + (size_t)r0 * DD;
    const __half* Bp = g_WeffTh + (size_t)b_ * DD * DD + (size_t)jb * DK * DD;
    const uint32_t smb = smem_u32(sm);

    GEMM_MAIN(Ap, Bp)

    float2 bev[8];
    #pragma unroll
    for (int nt = 0; nt < 8; nt++)
        bev[nt] = *(const float2*)&g_beff[(size_t)b_ * DD + jb * DK
                                          + wn * 64 + nt * 8 + tig * 2];
    #pragma unroll
    for (int mt = 0; mt < 4; mt++)
        #pragma unroll
        for (int h = 0; h < 2; h++) {
            int row = wm * 64 + mt * 16 + gid + h * 8;
            float* op = outp + (size_t)(r0 + row) * DD + jb * DK;
            #pragma unroll
            for (int nt = 0; nt < 8; nt++) {
                float2 o;
                o.x = acc[mt][nt][2 * h + 0] + bev[nt].x;
                o.y = acc[mt][nt][2 * h + 1] + bev[nt].y;
                *(float2*)(op + wn * 64 + nt * 8 + tig * 2) = o;
            }
        }
}

// ---------------------------------------------------------------------------
// scores: 3-stage cp.async, ONE sync per 32-row chunk; SPLITS=16.
// ---------------------------------------------------------------------------
__global__ __launch_bounds__(256)
void scores_h()
{
    extern __shared__ float sm[];
    const int split = blockIdx.x;
    const int bh    = blockIdx.y;
    const int tid = threadIdx.x;
    const int warp = tid >> 5, lane = tid & 31;
    const int wm = warp >> 1, wn = warp & 1;
    const int gid = lane >> 2, tig = lane & 3;

    const size_t base = (size_t)bh * NN * DK + (size_t)split * CHS * DK;
    const uint32_t smb = smem_u32(sm);

    float acc[2][8][4];
    #pragma unroll
    for (int mt = 0; mt < 2; mt++)
        #pragma unroll
        for (int nt = 0; nt < 8; nt++)
            #pragma unroll
            for (int i = 0; i < 4; i++) acc[mt][nt][i] = 0.f;

    auto load_stage = [&](int kc, int s) {
        uint32_t kb = smb + (uint32_t)s * 16384u;
        const __half* gk = g_Knh + base + (size_t)kc * 32 * DK;
        const __half* gv = g_Vnh + base + (size_t)kc * 32 * DK;
        #pragma unroll
        for (int u = 0; u < 2; u++) {
            int idx = u * 256 + tid;
            int row = idx >> 4, ch = idx & 15;
            uint32_t off = (uint32_t)(row * 256 + ((ch ^ (row & 7)) << 4));
            cp16(kb + off,          gk + (size_t)row * DK + ch * 8);
            cp16(kb + 8192u + off,  gv + (size_t)row * DK + ch * 8);
        }
        CP_COMMIT();
    };

    const int NCH = CHS / 32;   // 16 chunks
    load_stage(0, 0);
    load_stage(1, 1);

    for (int kc = 0; kc < NCH; kc++) {
        if (kc < NCH - 1) { CP_WAIT(1); } else { CP_WAIT(0); }
        __syncthreads();
        if (kc + 2 < NCH) load_stage(kc + 2, (kc + 2) % 3);

        uint32_t kb = smb + (uint32_t)(kc % 3) * 16384u;
        uint32_t vb = kb + 8192u;
        #pragma unroll
        for (int step = 0; step < 2; step++) {
            int n0 = step * 16;
            uint32_t afr[2][4];
            #pragma unroll
            for (int mt = 0; mt < 2; mt++) {
                int m0 = wm * 32 + mt * 16;
                int r = n0 + ((lane >> 4) << 3) + (lane & 7);
                int c = (m0 >> 3) + ((lane >> 3) & 1);
                ldsm4t(afr[mt], kb + r * 256 + ((c ^ (r & 7)) << 4));
            }
            #pragma unroll
            for (int eb = 0; eb < 4; eb++) {
                int e0 = wn * 64 + eb * 16;
                int r = n0 + (((lane >> 3) & 1) << 3) + (lane & 7);
                int c = (e0 >> 3) + (lane >> 4);
                uint32_t bfr[4];
                ldsm4t(bfr, vb + r * 256 + ((c ^ (r & 7)) << 4));
                mma16(acc[0][eb * 2],     afr[0], bfr);
                mma16(acc[0][eb * 2 + 1], afr[0], bfr + 2);
                mma16(acc[1][eb * 2],     afr[1], bfr);
                mma16(acc[1][eb * 2 + 1], afr[1], bfr + 2);
            }
        }
    }

    size_t pbase = ((size_t)split * (BB * HH) + bh) * DK * DK;
    #pragma unroll
    for (int mt = 0; mt < 2; mt++)
        #pragma unroll
        for (int h = 0; h < 2; h++) {
            int row = wm * 32 + mt * 16 + gid + h * 8;
            #pragma unroll
            for (int nt = 0; nt < 8; nt++) {
                float2 o;
                o.x = acc[mt][nt][2 * h + 0];
                o.y = acc[mt][nt][2 * h + 1];
                *(float2*)&g_Spart[pbase + (size_t)row * DK
                                   + wn * 64 + nt * 8 + tig * 2] = o;
            }
        }
}

__global__ void reduce_scores_kernel(float* __restrict__ p_out)
{
    int i = blockIdx.x * 256 + threadIdx.x;
    float s = 0.f;
    #pragma unroll
    for (int sp = 0; sp < SPLITS; sp++)
        s += g_Spart[(size_t)sp * (BB * HH * DK * DK) + i];
    p_out[i] = s * (1.f / NN);
}

__global__ void beff_kernel(const float* __restrict__ bq, const float* __restrict__ p)
{
    int bh = blockIdx.x;
    int e  = threadIdx.x;
    int h  = bh & (HH - 1), b_ = bh >> 3;
    const float* pp = p + (size_t)bh * DK * DK;
    float s = 0.f;
    #pragma unroll 8
    for (int d = 0; d < DK; d++) s += bq[h * DK + d] * pp[(size_t)d * DK + e];
    g_beff[(size_t)b_ * DD + h * DK + e] = s;
}

__global__ __launch_bounds__(256)
void weff_kernel(const float* __restrict__ Wq, const float* __restrict__ p)
{
    const int c0 = blockIdx.x * 64;
    const int bh = blockIdx.y;
    const int h = bh & (HH - 1), b_ = bh >> 3;
    const int tid = threadIdx.x;
    const int ty = tid >> 4, tx = tid & 15;

    __shared__ float As[16][64];
    __shared__ float Bs[16][128];

    float acc[4][8];
    #pragma unroll
    for (int i = 0; i < 4; i++)
        #pragma unroll
        for (int j = 0; j < 8; j++) acc[i][j] = 0.f;

    const int ak = tid >> 4;
    const int ar = (tid & 15) * 4;
    const int bk = tid >> 4;
    const int bc = (tid & 15) * 8;

    for (int k0 = 0; k0 < DK; k0 += 16) {
        *(float4*)&As[ak][ar] =
            *(const float4*)&Wq[(size_t)(h * DK + k0 + ak) * DD + c0 + ar];
        const float* pp = &p[(size_t)bh * DK * DK + (size_t)(k0 + bk) * DK + bc];
        *(float4*)&Bs[bk][bc]     = *(const float4*)pp;
        *(float4*)&Bs[bk][bc + 4] = *(const float4*)(pp + 4);
        __syncthreads();

        #pragma unroll
        for (int kk = 0; kk < 16; kk++) {
            float a[4], b[8];
            *(float4*)a       = *(const float4*)&As[kk][ty * 4];
            *(float4*)b       = *(const float4*)&Bs[kk][tx * 8];
            *(float4*)(b + 4) = *(const float4*)&Bs[kk][tx * 8 + 4];
            #pragma unroll
            for (int i = 0; i < 4; i++)
                #pragma unroll
                for (int j = 0; j < 8; j++) acc[i][j] += a[i] * b[j];
        }
        __syncthreads();
    }

    #pragma unroll
    for (int i = 0; i < 4; i++)
        #pragma unroll
        for (int j = 0; j < 8; j++)
            g_WeffTh[(size_t)b_ * DD * DD
                     + (size_t)(h * DK + tx * 8 + j) * DD + (c0 + ty * 4 + i)]
                = __float2half_rn(acc[i][j]);
}

extern "C" void kernel_launch(void* const* d_in, const int* in_sizes, int n_in,
                              void* d_out, int out_size)
{
    const float* q   = (const float*)d_in[0];
    const float* k   = (const float*)d_in[1];
    const float* v   = (const float*)d_in[2];
    const float* Wq  = (const float*)d_in[3];
    const float* bq  = (const float*)d_in[4];
    const float* Wk  = (const float*)d_in[5];
    const float* bk  = (const float*)d_in[6];
    const float* Wv  = (const float*)d_in[7];
    const float* bv  = (const float*)d_in[8];
    const float* gK  = (const float*)d_in[9];
    const float* beK = (const float*)d_in[10];
    const float* gV  = (const float*)d_in[11];
    const float* beV = (const float*)d_in[12];

    float* out   = (float*)d_out;
    float* p_out = out + (size_t)BN * DD;

    static bool init_done = false;
    if (!init_done) {
        cudaFuncSetAttribute(gemm_kv,  cudaFuncAttributeMaxDynamicSharedMemorySize, GEMM_SMEM);
        cudaFuncSetAttribute(gemm_fin, cudaFuncAttributeMaxDynamicSharedMemorySize, GEMM_SMEM);
        cudaFuncSetAttribute(scores_h, cudaFuncAttributeMaxDynamicSharedMemorySize, SC_SMEM);
        init_done = true;
    }

    const int n8_w = (DD * DD) / 8;
    f2h_w<<<(2 * n8_w) / 256, 256>>>(Wk, Wv, n8_w);

    gemm_kv<<<dim3(2 * HH, BN / 128), 128, GEMM_SMEM>>>(k, v, bk, gK, beK, bv, gV, beV);
    scores_h<<<dim3(SPLITS, BB * HH), 256, SC_SMEM>>>();
    reduce_scores_kernel<<<dim3((BB * HH * DK * DK) / 256), 256>>>(p_out);
    beff_kernel<<<dim3(BB * HH), dim3(DK)>>>(bq, p_out);
    weff_kernel<<<dim3(DD / 64, BB * HH), 256>>>(Wq, p_out);
    gemm_fin<<<dim3(HH, BN / 128), 128, GEMM_SMEM>>>(q, out);
}